// round 7
// baseline (speedup 1.0000x reference)
#include <cuda_runtime.h>

typedef unsigned long long ull;

#define Lg 64
#define Bg 1024
#define THp 8
#define NTILES (Lg/THp)         // 8
#define THREADS 384
#define R1 (THp+4)              // 12 conv1 output rows (halo 2)
#define R2 (THp+2)              // 10 conv2 output rows (halo 1)
#define RZ (THp+6)              // 14 input rows (halo 3)
#define PW1 34                  // pairs per row with wrapped halo (p = -1..32)
#define PW2 32                  // S2: no halo entries

// ---- shared memory layout (ull units) ----
#define S1U 0                               // 16*12*34 = 6528
#define S2U (S1U + 16*R1*PW1)               // 6528 (+16*10*32 = 5120)
#define SZU S2U                             // SZ overlays S2 (disjoint lifetime)
#define WU1 (S2U + 16*R2*PW2)               // 11648 (2304)
#define WU0 (WU1 + 2304)                    // 13952 (144)
#define WU2 (WU0 + 144)                     // 14096 (144)
#define BFU (WU2 + 144)                     // 14240 (biases: 33 floats -> 20 ull)
#define U_TOTAL (BFU + 20)                  // 14260
#define SMEM_BYTES ((size_t)U_TOTAL * 8)    // 114080 B  (2 CTAs/SM)

// ---- packed f32x2 helpers (sm_100+) : per-lane exact fp32 FMA ----
__device__ __forceinline__ ull pk(float lo, float hi) {
    ull r; asm("mov.b64 %0, {%1, %2};" : "=l"(r) : "f"(lo), "f"(hi)); return r;
}
__device__ __forceinline__ void upk(ull v, float& lo, float& hi) {
    asm("mov.b64 {%0, %1}, %2;" : "=f"(lo), "=f"(hi) : "l"(v));
}
__device__ __forceinline__ void fma2(ull& d, ull a, ull b) {
    asm("fma.rn.f32x2 %0, %1, %2, %0;" : "+l"(d) : "l"(a), "l"(b));
}
__device__ __forceinline__ ull swap32(ull v) { return (v >> 32) | (v << 32); }

// XLA EmitFastTanh replica. DO NOT CHANGE (bit-exactness verified).
__device__ __forceinline__ float xla_tanh(float x) {
    float ax = fabsf(x);
    float xc = fminf(fmaxf(x, -9.0f), 9.0f);
    float x2 = __fmul_rn(xc, xc);
    float p = -2.76076847742355e-16f;
    p = __fmaf_rn(p, x2,  2.00018790482477e-13f);
    p = __fmaf_rn(p, x2, -8.60467152213735e-11f);
    p = __fmaf_rn(p, x2,  5.12229709037114e-08f);
    p = __fmaf_rn(p, x2,  1.48572235717979e-05f);
    p = __fmaf_rn(p, x2,  6.37261928875436e-04f);
    p = __fmaf_rn(p, x2,  4.89352455891786e-03f);
    float num = __fmul_rn(xc, p);
    float q =  1.19825839466702e-06f;
    q = __fmaf_rn(q, x2,  1.18534705686654e-04f);
    q = __fmaf_rn(q, x2,  2.26843463243900e-03f);
    q = __fmaf_rn(q, x2,  4.89352518554385e-03f);
    float r = __fdiv_rn(num, q);
    return (ax < 0.0004f) ? x : r;
}

__global__ void copy_k(const float4* __restrict__ in, float4* __restrict__ out) {
    int i = blockIdx.x * blockDim.x + threadIdx.x;
    out[i] = in[i];
}

// One fused layer. All conv accumulations are single fp32 FMA chains from 0
// in k = (dy, dx, ci) order (ci fastest), bias after — bit-identical to XLA.
__global__ void __launch_bounds__(THREADS, 2)
layer_kernel(float* __restrict__ x,
             const float* __restrict__ w0, const float* __restrict__ b0,
             const float* __restrict__ w1, const float* __restrict__ b1,
             const float* __restrict__ w2, const float* __restrict__ b2,
             int parity)
{
    extern __shared__ ull su[];
    float* sb = (float*)(su + BFU);      // sb[0..15]=b0, [16..31]=b1, [32]=b2

    const int tid   = threadIdx.x;
    const int rbase = blockIdx.x * THp;                // even
    const int xbase = ((int)blockIdx.y) << 12;         // b*4096

    // ---- Phase 0: weights as duplicated (w,w) pairs + biases + packed input ----
    for (int t = tid; t < 2304; t += THREADS) { float w = w1[t]; su[WU1 + t] = pk(w, w); }
    if (tid < 144) {
        float a = w0[tid], b = w2[tid];
        su[WU0 + tid] = pk(a, a);
        su[WU2 + tid] = pk(b, b);
    }
    if (tid >= 160 && tid < 176) { int i = tid - 160; sb[i] = b0[i]; }
    if (tid >= 192 && tid < 208) { int i = tid - 192; sb[16 + i] = b1[i]; }
    if (tid == 224) { sb[32] = b2[0]; }

    // packed masked input (overlaid on S2 region): entry e of row rr holds
    // pair p = e-1: ( z[gr][p&63], z[gr][(p+32)&63] ), zeroed at non-A sites.
    for (int t = tid; t < RZ * PW1; t += THREADS) {
        int rr = t / PW1, e = t - rr * PW1, p = e - 1;
        int gr = (rbase + rr - 3) & 63;
        int c0 = p & 63, c1 = (p + 32) & 63;
        const float* row = x + xbase + (gr << 6);
        float v0 = row[c0], v1 = row[c1];
        v0 = (((gr + c0) & 1) == parity) ? v0 : 0.0f;
        v1 = (((gr + c1) & 1) == parity) ? v1 : 0.0f;
        su[SZU + t] = pk(v0, v1);
    }
    __syncthreads();

    // ---- Phase 1: conv1 (1 -> 16), chain (dy,dx), bias, tanh ----
    // EXACTLY 384 tasks: 12 rows x 16 pair-lanes x 2 co-halves (one per thread)
    {
        int rr = tid >> 5, rem = tid & 31;
        int pA = rem & 15, pB = pA + 16;
        int coB = (rem >> 4) << 3;
        ull acc[16];
        #pragma unroll
        for (int i = 0; i < 16; i++) acc[i] = 0ull;
        #pragma unroll
        for (int dy = 0; dy < 3; dy++) {
            const ull* rp = su + SZU + (rr + dy) * PW1 + 1;
            #pragma unroll
            for (int dx = 0; dx < 3; dx++) {
                ull qa = rp[pA + dx - 1];
                ull qb = rp[pB + dx - 1];
                const ull* wp = su + WU0 + (dy * 3 + dx) * 16 + coB;
                #pragma unroll
                for (int j = 0; j < 4; j++) {
                    ulonglong2 wv = *(const ulonglong2*)(wp + 2 * j);
                    fma2(acc[4*j + 0], wv.x, qa);
                    fma2(acc[4*j + 1], wv.x, qb);
                    fma2(acc[4*j + 2], wv.y, qa);
                    fma2(acc[4*j + 3], wv.y, qb);
                }
            }
        }
        #pragma unroll
        for (int j = 0; j < 8; j++) {
            int co = coB + j;
            float bb = sb[co];
            ull aA = acc[((j >> 1) << 2) + ((j & 1) << 1)];
            ull aB = acc[((j >> 1) << 2) + ((j & 1) << 1) + 1];
            float uA0, uA1, uB0, uB1;
            upk(aA, uA0, uA1); upk(aB, uB0, uB1);
            float tA0 = xla_tanh(__fadd_rn(uA0, bb));
            float tA1 = xla_tanh(__fadd_rn(uA1, bb));
            float tB0 = xla_tanh(__fadd_rn(uB0, bb));
            float tB1 = xla_tanh(__fadd_rn(uB1, bb));
            ull* op = su + S1U + (co * R1 + rr) * PW1 + 1;
            op[pA] = pk(tA0, tA1);
            op[pB] = pk(tB0, tB1);
            if (pA == 15) op[-1] = pk(tB1, tB0);   // halo = swap(pair 31)
            if (pA == 0)  op[32] = pk(tA1, tA0);   // halo = swap(pair 0)
        }
    }
    __syncthreads();

    // ---- Phase 2: conv2 (16 -> 16), chain (dy,dx,ci), bias, tanh ----
    // 320 tasks: 10 rows x 16 pair-lanes x 2 co-halves (writes S2, no halo)
    if (tid < R2 * 32) {
        int rr = tid >> 5, rem = tid & 31;
        int pA = rem & 15, pB = pA + 16;
        int coB = (rem >> 4) << 3;
        ull acc[16];
        #pragma unroll
        for (int i = 0; i < 16; i++) acc[i] = 0ull;
        #pragma unroll
        for (int dy = 0; dy < 3; dy++) {
            const ull* rbp = su + S1U + (rr + dy) * PW1 + 1;
            #pragma unroll
            for (int dx = 0; dx < 3; dx++) {
                const ull* wb = su + WU1 + (dy * 3 + dx) * 256 + coB;
                #pragma unroll 4
                for (int ci = 0; ci < 16; ci++) {
                    const ull* rp = rbp + ci * (R1 * PW1);
                    ull qa = rp[pA + dx - 1];
                    ull qb = rp[pB + dx - 1];
                    const ull* wp = wb + ci * 16;
                    ulonglong2 w01 = *(const ulonglong2*)(wp);
                    ulonglong2 w23 = *(const ulonglong2*)(wp + 2);
                    ulonglong2 w45 = *(const ulonglong2*)(wp + 4);
                    ulonglong2 w67 = *(const ulonglong2*)(wp + 6);
                    fma2(acc[0],  w01.x, qa); fma2(acc[1],  w01.x, qb);
                    fma2(acc[2],  w01.y, qa); fma2(acc[3],  w01.y, qb);
                    fma2(acc[4],  w23.x, qa); fma2(acc[5],  w23.x, qb);
                    fma2(acc[6],  w23.y, qa); fma2(acc[7],  w23.y, qb);
                    fma2(acc[8],  w45.x, qa); fma2(acc[9],  w45.x, qb);
                    fma2(acc[10], w45.y, qa); fma2(acc[11], w45.y, qb);
                    fma2(acc[12], w67.x, qa); fma2(acc[13], w67.x, qb);
                    fma2(acc[14], w67.y, qa); fma2(acc[15], w67.y, qb);
                }
            }
        }
        #pragma unroll
        for (int j = 0; j < 8; j++) {
            int co = coB + j;
            float bb = sb[16 + co];
            float uA0, uA1, uB0, uB1;
            upk(acc[2*j], uA0, uA1); upk(acc[2*j + 1], uB0, uB1);
            float tA0 = xla_tanh(__fadd_rn(uA0, bb));
            float tA1 = xla_tanh(__fadd_rn(uA1, bb));
            float tB0 = xla_tanh(__fadd_rn(uB0, bb));
            float tB1 = xla_tanh(__fadd_rn(uB1, bb));
            ull* op = su + S2U + (co * R2 + rr) * PW2;
            op[pA] = pk(tA0, tA1);
            op[pB] = pk(tB0, tB1);
        }
    }
    __syncthreads();

    // ---- Phase 3: conv3 (16 -> 1), chain (dy,dx,ci), bias, STE sign update ----
    // 256 tasks: 8 rows x 32 pairs; pair p0 covers columns (p0, p0+32).
    // S2 has no halo entries: wrap lanes use precomputed index + 32-bit rotate
    // (pair(-1) == swap(pair 31), pair(32) == swap(pair 0)).
    if (tid < THp * 32) {
        int rr = tid >> 5;
        int p0 = tid & 31;
        int qm = (p0 == 0)  ? 31 : (p0 - 1);
        int qp = (p0 == 31) ? 0  : (p0 + 1);
        bool swm = (p0 == 0), swp = (p0 == 31);
        ull acc = 0ull;
        #pragma unroll
        for (int dy = 0; dy < 3; dy++) {
            #pragma unroll
            for (int dx = 0; dx < 3; dx++) {
                const ull* wp = su + WU2 + (dy * 3 + dx) * 16;
                #pragma unroll 4
                for (int ci = 0; ci < 16; ci++) {
                    const ull* rp = su + S2U + (ci * R2 + rr + dy) * PW2;
                    ull v;
                    if (dx == 0)      { v = rp[qm]; v = swm ? swap32(v) : v; }
                    else if (dx == 1) { v = rp[p0]; }
                    else              { v = rp[qp]; v = swp ? swap32(v) : v; }
                    fma2(acc, wp[ci], v);
                }
            }
        }
        float bb = sb[32];
        float u0, u1;
        upk(acc, u0, u1);
        float l0 = __fadd_rn(u0, bb);
        float l1 = __fadd_rn(u1, bb);
        int gr = rbase + rr;
        // columns p0 and p0+32 share parity -> uniform condition per thread
        if (((gr + p0) & 1) != parity) {
            float* row = x + xbase + (gr << 6);
            float s0 = (l0 > 0.0f) ? 1.0f : ((l0 < 0.0f) ? -1.0f : 0.0f);
            float s1v = (l1 > 0.0f) ? 1.0f : ((l1 < 0.0f) ? -1.0f : 0.0f);
            // STE forward exactly as XLA computes it: l + (sign(l) - l)
            float m0 = __fadd_rn(l0, __fadd_rn(s0, -l0));
            float m1 = __fadd_rn(l1, __fadd_rn(s1v, -l1));
            row[p0]      = __fmul_rn(row[p0],      m0);
            row[p0 + 32] = __fmul_rn(row[p0 + 32], m1);
        }
    }
}

extern "C" void kernel_launch(void* const* d_in, const int* in_sizes, int n_in,
                              void* d_out, int out_size)
{
    const float* z  = (const float*)d_in[0];
    const float* W0 = (const float*)d_in[1];
    const float* b0 = (const float*)d_in[2];
    const float* W1 = (const float*)d_in[3];
    const float* b1 = (const float*)d_in[4];
    const float* W2 = (const float*)d_in[5];
    const float* b2 = (const float*)d_in[6];
    float* x = (float*)d_out;

    cudaFuncSetAttribute(layer_kernel, cudaFuncAttributeMaxDynamicSharedMemorySize,
                         (int)SMEM_BYTES);

    // reset working state each replay: x <- z
    copy_k<<<(Bg * Lg * Lg) / (4 * 256), 256>>>((const float4*)z, (float4*)x);

    for (int i = 0; i < 4; i++) {
        layer_kernel<<<dim3(NTILES, Bg), THREADS, SMEM_BYTES>>>(
            x,
            W0 + i * 144, b0 + i * 16,
            W1 + i * 2304, b1 + i * 16,
            W2 + i * 144, b2 + i,
            i & 1);
    }
}

// round 8
// speedup vs baseline: 1.1359x; 1.1359x over previous
#include <cuda_runtime.h>

typedef unsigned long long ull;

#define Lg 64
#define Bg 1024
#define TH 16
#define NTILES (Lg/TH)          // 4
#define THREADS 640
#define R1 (TH+4)               // 20 conv1 output rows (halo 2)
#define R2 (TH+2)               // 18 conv2 output rows (halo 1)
#define RZ (TH+6)               // 22 input rows (halo 3)
#define PW 34                   // pairs per row: p = -1..32 (wrapped halo)

// ---- shared memory layout (ull units) ----
#define S1U 0                               // 16*20*34 = 10880
#define S2U (S1U + 16*R1*PW)                // 10880 (+9792)
#define SZU (S2U + 16*R2*PW)                // 20672 (+748)
#define WU1 (SZU + RZ*PW)                   // 21420 (2304)
#define WU0 (WU1 + 2304)                    // 23724 (144)
#define WU2 (WU0 + 144)                     // 23868 (144)
#define BFU (WU2 + 144)                     // 24012 (packed biases: 33 ull)
#define U_TOTAL (BFU + 33)                  // 24045
#define SMEM_BYTES ((size_t)U_TOTAL * 8)    // 192360 B

// ---- packed f32x2 helpers (sm_100+) : per-lane exact fp32 ops ----
__device__ __forceinline__ ull pk(float lo, float hi) {
    ull r; asm("mov.b64 %0, {%1, %2};" : "=l"(r) : "f"(lo), "f"(hi)); return r;
}
__device__ __forceinline__ void upk(ull v, float& lo, float& hi) {
    asm("mov.b64 {%0, %1}, %2;" : "=f"(lo), "=f"(hi) : "l"(v));
}
__device__ __forceinline__ void fma2(ull& d, ull a, ull b) {   // d += a*b
    asm("fma.rn.f32x2 %0, %1, %2, %0;" : "+l"(d) : "l"(a), "l"(b));
}
__device__ __forceinline__ void fma2h(ull& d, ull a, ull c) {  // d = d*a + c
    asm("fma.rn.f32x2 %0, %0, %1, %2;" : "+l"(d) : "l"(a), "l"(c));
}
__device__ __forceinline__ ull add2(ull a, ull b) {
    ull r; asm("add.rn.f32x2 %0, %1, %2;" : "=l"(r) : "l"(a), "l"(b)); return r;
}
__device__ __forceinline__ ull mul2(ull a, ull b) {
    ull r; asm("mul.rn.f32x2 %0, %1, %2;" : "=l"(r) : "l"(a), "l"(b)); return r;
}
__device__ __forceinline__ ull dup(float f) { return pk(f, f); }
__device__ __forceinline__ ull swap32(ull v) { return (v >> 32) | (v << 32); }

// Packed XLA EmitFastTanh on an accumulator pair + packed bias.
// Per-lane op sequence identical to the verified scalar replica:
//   s = fl(acc+b); clamp +-9 (alu); x2 = s*s; Horner p,q (packed fma = per-lane
//   exact rn); num = xc*p; r = div.rn(num,q); |s|<4e-4 passthrough.
// DO NOT CHANGE the op sequence (bit-exactness vs XLA verified).
__device__ __forceinline__ ull xla_tanh2(ull acc, ull bias2) {
    ull s = add2(acc, bias2);
    float s0, s1; upk(s, s0, s1);
    float xc0 = fminf(fmaxf(s0, -9.0f), 9.0f);
    float xc1 = fminf(fmaxf(s1, -9.0f), 9.0f);
    ull xc = pk(xc0, xc1);
    ull x2 = mul2(xc, xc);
    ull p = dup(-2.76076847742355e-16f);
    fma2h(p, x2, dup( 2.00018790482477e-13f));
    fma2h(p, x2, dup(-8.60467152213735e-11f));
    fma2h(p, x2, dup( 5.12229709037114e-08f));
    fma2h(p, x2, dup( 1.48572235717979e-05f));
    fma2h(p, x2, dup( 6.37261928875436e-04f));
    fma2h(p, x2, dup( 4.89352455891786e-03f));
    ull num = mul2(xc, p);
    ull q = dup(1.19825839466702e-06f);
    fma2h(q, x2, dup(1.18534705686654e-04f));
    fma2h(q, x2, dup(2.26843463243900e-03f));
    fma2h(q, x2, dup(4.89352518554385e-03f));
    float n0, n1, q0, q1;
    upk(num, n0, n1); upk(q, q0, q1);
    float r0 = __fdiv_rn(n0, q0);
    float r1 = __fdiv_rn(n1, q1);
    float t0 = (fabsf(s0) < 0.0004f) ? s0 : r0;
    float t1 = (fabsf(s1) < 0.0004f) ? s1 : r1;
    return pk(t0, t1);
}

__global__ void copy_k(const float4* __restrict__ in, float4* __restrict__ out) {
    int i = blockIdx.x * blockDim.x + threadIdx.x;
    out[i] = in[i];
}

// One fused layer. All conv accumulations are single fp32 FMA chains from 0
// in k = (dy, dx, ci) order (ci fastest), bias after — bit-identical to XLA.
__global__ void __launch_bounds__(THREADS, 1)
layer_kernel(float* __restrict__ x,
             const float* __restrict__ w0, const float* __restrict__ b0,
             const float* __restrict__ w1, const float* __restrict__ b1,
             const float* __restrict__ w2, const float* __restrict__ b2,
             int parity)
{
    extern __shared__ ull su[];

    const int tid   = threadIdx.x;
    const int rbase = blockIdx.x * TH;                 // even
    const int xbase = ((int)blockIdx.y) << 12;         // b*4096

    // ---- Phase 0: weights as duplicated (w,w) pairs + packed biases + input ----
    for (int t = tid; t < 2304; t += THREADS) { float w = w1[t]; su[WU1 + t] = pk(w, w); }
    if (tid < 144) {
        float a = w0[tid], b = w2[tid];
        su[WU0 + tid] = pk(a, a);
        su[WU2 + tid] = pk(b, b);
    }
    if (tid >= 160 && tid < 176) { int i = tid - 160; float v = b0[i]; su[BFU + i] = pk(v, v); }
    if (tid >= 192 && tid < 208) { int i = tid - 192; float v = b1[i]; su[BFU + 16 + i] = pk(v, v); }
    if (tid == 224) { float v = b2[0]; su[BFU + 32] = pk(v, v); }

    // packed masked input: entry e of row rr holds pair p = e-1:
    // ( z[gr][p&63], z[gr][(p+32)&63] ), zeroed at non-A sites.
    for (int t = tid; t < RZ * PW; t += THREADS) {
        int rr = t / PW, e = t - rr * PW, p = e - 1;
        int gr = (rbase + rr - 3) & 63;
        int c0 = p & 63, c1 = (p + 32) & 63;
        const float* row = x + xbase + (gr << 6);
        float v0 = row[c0], v1 = row[c1];
        v0 = (((gr + c0) & 1) == parity) ? v0 : 0.0f;
        v1 = (((gr + c1) & 1) == parity) ? v1 : 0.0f;
        su[SZU + t] = pk(v0, v1);
    }
    __syncthreads();

    // ---- Phase 1: conv1 (1 -> 16), chain (dy,dx), bias, tanh ----
    // EXACTLY 640 tasks: 20 rows x 16 pair-lanes x 2 co-halves (one per thread)
    {
        int rr = tid >> 5, rem = tid & 31;
        int pA = rem & 15, pB = pA + 16;
        int coB = (rem >> 4) << 3;
        ull acc[16];
        #pragma unroll
        for (int i = 0; i < 16; i++) acc[i] = 0ull;
        #pragma unroll
        for (int dy = 0; dy < 3; dy++) {
            const ull* rp = su + SZU + (rr + dy) * PW + 1;
            #pragma unroll
            for (int dx = 0; dx < 3; dx++) {
                ull qa = rp[pA + dx - 1];
                ull qb = rp[pB + dx - 1];
                const ull* wp = su + WU0 + (dy * 3 + dx) * 16 + coB;
                #pragma unroll
                for (int j = 0; j < 4; j++) {
                    ulonglong2 wv = *(const ulonglong2*)(wp + 2 * j);
                    fma2(acc[4*j + 0], wv.x, qa);
                    fma2(acc[4*j + 1], wv.x, qb);
                    fma2(acc[4*j + 2], wv.y, qa);
                    fma2(acc[4*j + 3], wv.y, qb);
                }
            }
        }
        #pragma unroll
        for (int j = 0; j < 8; j++) {
            int co = coB + j;
            ull b2v = su[BFU + co];
            ull aA = acc[((j >> 1) << 2) + ((j & 1) << 1)];
            ull aB = acc[((j >> 1) << 2) + ((j & 1) << 1) + 1];
            ull rA = xla_tanh2(aA, b2v);
            ull rB = xla_tanh2(aB, b2v);
            ull* op = su + S1U + (co * R1 + rr) * PW + 1;
            op[pA] = rA;
            op[pB] = rB;
            if (pA == 15) op[-1] = swap32(rB);   // halo = swap(pair 31)
            if (pA == 0)  op[32] = swap32(rA);   // halo = swap(pair 0)
        }
    }
    __syncthreads();

    // ---- Phase 2: conv2 (16 -> 16), chain (dy,dx,ci), bias, tanh ----
    // EXACTLY 640 tasks, SMSP-balanced: rows 0..15 heavy (2pp x 8co, 512),
    // rows 16..17 light (1pp x 8co, 128). Every SMSP: 4 heavy + 1 light warp.
    if (tid < 512) {
        int rr = tid >> 5, rem = tid & 31;
        int pA = rem & 15, pB = pA + 16;
        int coB = (rem >> 4) << 3;
        ull acc[16];
        #pragma unroll
        for (int i = 0; i < 16; i++) acc[i] = 0ull;
        #pragma unroll
        for (int dy = 0; dy < 3; dy++) {
            const ull* rbp = su + S1U + (rr + dy) * PW + 1;
            #pragma unroll
            for (int dx = 0; dx < 3; dx++) {
                const ull* wb = su + WU1 + (dy * 3 + dx) * 256 + coB;
                #pragma unroll 8
                for (int ci = 0; ci < 16; ci++) {
                    const ull* rp = rbp + ci * (R1 * PW);
                    ull qa = rp[pA + dx - 1];
                    ull qb = rp[pB + dx - 1];
                    const ull* wp = wb + ci * 16;
                    ulonglong2 w01 = *(const ulonglong2*)(wp);
                    ulonglong2 w23 = *(const ulonglong2*)(wp + 2);
                    ulonglong2 w45 = *(const ulonglong2*)(wp + 4);
                    ulonglong2 w67 = *(const ulonglong2*)(wp + 6);
                    fma2(acc[0],  w01.x, qa); fma2(acc[1],  w01.x, qb);
                    fma2(acc[2],  w01.y, qa); fma2(acc[3],  w01.y, qb);
                    fma2(acc[4],  w23.x, qa); fma2(acc[5],  w23.x, qb);
                    fma2(acc[6],  w23.y, qa); fma2(acc[7],  w23.y, qb);
                    fma2(acc[8],  w45.x, qa); fma2(acc[9],  w45.x, qb);
                    fma2(acc[10], w45.y, qa); fma2(acc[11], w45.y, qb);
                    fma2(acc[12], w67.x, qa); fma2(acc[13], w67.x, qb);
                    fma2(acc[14], w67.y, qa); fma2(acc[15], w67.y, qb);
                }
            }
        }
        #pragma unroll
        for (int j = 0; j < 8; j++) {
            int co = coB + j;
            ull b2v = su[BFU + 16 + co];
            ull rA = xla_tanh2(acc[2*j],     b2v);
            ull rB = xla_tanh2(acc[2*j + 1], b2v);
            ull* op = su + S2U + (co * R2 + rr) * PW + 1;
            op[pA] = rA;
            op[pB] = rB;
            if (pA == 15) op[-1] = swap32(rB);
            if (pA == 0)  op[32] = swap32(rA);
        }
    } else {
        int t = tid - 512;                       // 0..127
        int rr = 16 + (t >> 6);                  // rows 16..17
        int rem = t & 63;
        int p0 = rem >> 1;                       // 0..31
        int coB = (rem & 1) << 3;
        ull acc[8];
        #pragma unroll
        for (int i = 0; i < 8; i++) acc[i] = 0ull;
        #pragma unroll
        for (int dy = 0; dy < 3; dy++) {
            const ull* rbp = su + S1U + (rr + dy) * PW + 1;
            #pragma unroll
            for (int dx = 0; dx < 3; dx++) {
                const ull* wb = su + WU1 + (dy * 3 + dx) * 256 + coB;
                #pragma unroll 8
                for (int ci = 0; ci < 16; ci++) {
                    const ull* rp = rbp + ci * (R1 * PW);
                    ull qa = rp[p0 + dx - 1];
                    const ull* wp = wb + ci * 16;
                    ulonglong2 w01 = *(const ulonglong2*)(wp);
                    ulonglong2 w23 = *(const ulonglong2*)(wp + 2);
                    ulonglong2 w45 = *(const ulonglong2*)(wp + 4);
                    ulonglong2 w67 = *(const ulonglong2*)(wp + 6);
                    fma2(acc[0], w01.x, qa); fma2(acc[1], w01.y, qa);
                    fma2(acc[2], w23.x, qa); fma2(acc[3], w23.y, qa);
                    fma2(acc[4], w45.x, qa); fma2(acc[5], w45.y, qa);
                    fma2(acc[6], w67.x, qa); fma2(acc[7], w67.y, qa);
                }
            }
        }
        #pragma unroll
        for (int j = 0; j < 8; j++) {
            int co = coB + j;
            ull b2v = su[BFU + 16 + co];
            ull r = xla_tanh2(acc[j], b2v);
            ull* op = su + S2U + (co * R2 + rr) * PW + 1;
            op[p0] = r;
            if (p0 == 31) op[-1] = swap32(r);
            if (p0 == 0)  op[32] = swap32(r);
        }
    }
    __syncthreads();

    // ---- Phase 3: conv3 (16 -> 1), chain (dy,dx,ci), bias, STE sign update ----
    // 512 tasks: 16 rows x 32 pairs; pair p0 covers columns (p0, p0+32)
    if (tid < TH * 32) {
        int rr = tid >> 5;
        int p0 = tid & 31;
        ull acc = 0ull;
        #pragma unroll
        for (int dy = 0; dy < 3; dy++) {
            const ull* rbp = su + S2U + (rr + dy) * PW + 1;
            #pragma unroll
            for (int dx = 0; dx < 3; dx++) {
                const ull* wp = su + WU2 + (dy * 3 + dx) * 16;
                #pragma unroll 8
                for (int ci = 0; ci < 16; ci++) {
                    const ull* rp = rbp + ci * (R2 * PW);
                    fma2(acc, wp[ci], rp[p0 + dx - 1]);
                }
            }
        }
        float bb, dummy;
        upk(su[BFU + 32], bb, dummy);
        float u0, u1;
        upk(acc, u0, u1);
        float l0 = __fadd_rn(u0, bb);
        float l1 = __fadd_rn(u1, bb);
        int gr = rbase + rr;
        // columns p0 and p0+32 share parity -> uniform condition per thread
        if (((gr + p0) & 1) != parity) {
            float* row = x + xbase + (gr << 6);
            float s0 = (l0 > 0.0f) ? 1.0f : ((l0 < 0.0f) ? -1.0f : 0.0f);
            float s1v = (l1 > 0.0f) ? 1.0f : ((l1 < 0.0f) ? -1.0f : 0.0f);
            // STE forward exactly as XLA computes it: l + (sign(l) - l)
            float m0 = __fadd_rn(l0, __fadd_rn(s0, -l0));
            float m1 = __fadd_rn(l1, __fadd_rn(s1v, -l1));
            row[p0]      = __fmul_rn(row[p0],      m0);
            row[p0 + 32] = __fmul_rn(row[p0 + 32], m1);
        }
    }
}

extern "C" void kernel_launch(void* const* d_in, const int* in_sizes, int n_in,
                              void* d_out, int out_size)
{
    const float* z  = (const float*)d_in[0];
    const float* W0 = (const float*)d_in[1];
    const float* b0 = (const float*)d_in[2];
    const float* W1 = (const float*)d_in[3];
    const float* b1 = (const float*)d_in[4];
    const float* W2 = (const float*)d_in[5];
    const float* b2 = (const float*)d_in[6];
    float* x = (float*)d_out;

    cudaFuncSetAttribute(layer_kernel, cudaFuncAttributeMaxDynamicSharedMemorySize,
                         (int)SMEM_BYTES);

    // reset working state each replay: x <- z
    copy_k<<<(Bg * Lg * Lg) / (4 * 256), 256>>>((const float4*)z, (float4*)x);

    for (int i = 0; i < 4; i++) {
        layer_kernel<<<dim3(NTILES, Bg), THREADS, SMEM_BYTES>>>(
            x,
            W0 + i * 144, b0 + i * 16,
            W1 + i * 2304, b1 + i * 16,
            W2 + i * 144, b2 + i,
            i & 1);
    }
}

// round 9
// speedup vs baseline: 1.1657x; 1.0263x over previous
#include <cuda_runtime.h>

typedef unsigned long long ull;

#define Lg 64
#define Bg 1024
#define TH 16
#define NTILES (Lg/TH)          // 4
#define THREADS 640
#define R1 (TH+4)               // 20 conv1 output rows (halo 2)
#define R2 (TH+2)               // 18 conv2 output rows (halo 1)
#define RZ (TH+6)               // 22 input rows (halo 3)
#define PW 34                   // pairs per row: p = -1..32 (wrapped halo)

// ---- shared memory layout (ull units) ----
#define S1U 0                               // 16*20*34 = 10880
#define S2U (S1U + 16*R1*PW)                // 10880 (+9792)
#define SZU (S2U + 16*R2*PW)                // 20672 (+748)
#define WU1 (SZU + RZ*PW)                   // 21420 (2304)
#define WU0 (WU1 + 2304)                    // 23724 (144)
#define WU2 (WU0 + 144)                     // 23868 (144)
#define BFU (WU2 + 144)                     // 24012 (packed biases: 33 ull)
#define U_TOTAL (BFU + 33)                  // 24045
#define SMEM_BYTES ((size_t)U_TOTAL * 8)    // 192360 B

// ---- packed f32x2 helpers (sm_100+) : per-lane exact fp32 ops ----
__device__ __forceinline__ ull pk(float lo, float hi) {
    ull r; asm("mov.b64 %0, {%1, %2};" : "=l"(r) : "f"(lo), "f"(hi)); return r;
}
__device__ __forceinline__ void upk(ull v, float& lo, float& hi) {
    asm("mov.b64 {%0, %1}, %2;" : "=f"(lo), "=f"(hi) : "l"(v));
}
__device__ __forceinline__ void fma2(ull& d, ull a, ull b) {   // d += a*b
    asm("fma.rn.f32x2 %0, %1, %2, %0;" : "+l"(d) : "l"(a), "l"(b));
}
__device__ __forceinline__ void fma2h(ull& d, ull a, ull c) {  // d = d*a + c
    asm("fma.rn.f32x2 %0, %0, %1, %2;" : "+l"(d) : "l"(a), "l"(c));
}
__device__ __forceinline__ ull add2(ull a, ull b) {
    ull r; asm("add.rn.f32x2 %0, %1, %2;" : "=l"(r) : "l"(a), "l"(b)); return r;
}
__device__ __forceinline__ ull mul2(ull a, ull b) {
    ull r; asm("mul.rn.f32x2 %0, %1, %2;" : "=l"(r) : "l"(a), "l"(b)); return r;
}
__device__ __forceinline__ ull dup(float f) { return pk(f, f); }
__device__ __forceinline__ ull swap32(ull v) { return (v >> 32) | (v << 32); }

// Packed XLA EmitFastTanh on an accumulator pair + packed bias.
// Per-lane op sequence identical to the verified scalar replica.
// DO NOT CHANGE the op sequence (bit-exactness vs XLA verified).
__device__ __forceinline__ ull xla_tanh2(ull acc, ull bias2) {
    ull s = add2(acc, bias2);
    float s0, s1; upk(s, s0, s1);
    float xc0 = fminf(fmaxf(s0, -9.0f), 9.0f);
    float xc1 = fminf(fmaxf(s1, -9.0f), 9.0f);
    ull xc = pk(xc0, xc1);
    ull x2 = mul2(xc, xc);
    ull p = dup(-2.76076847742355e-16f);
    fma2h(p, x2, dup( 2.00018790482477e-13f));
    fma2h(p, x2, dup(-8.60467152213735e-11f));
    fma2h(p, x2, dup( 5.12229709037114e-08f));
    fma2h(p, x2, dup( 1.48572235717979e-05f));
    fma2h(p, x2, dup( 6.37261928875436e-04f));
    fma2h(p, x2, dup( 4.89352455891786e-03f));
    ull num = mul2(xc, p);
    ull q = dup(1.19825839466702e-06f);
    fma2h(q, x2, dup(1.18534705686654e-04f));
    fma2h(q, x2, dup(2.26843463243900e-03f));
    fma2h(q, x2, dup(4.89352518554385e-03f));
    float n0, n1, q0, q1;
    upk(num, n0, n1); upk(q, q0, q1);
    float r0 = __fdiv_rn(n0, q0);
    float r1 = __fdiv_rn(n1, q1);
    float t0 = (fabsf(s0) < 0.0004f) ? s0 : r0;
    float t1 = (fabsf(s1) < 0.0004f) ? s1 : r1;
    return pk(t0, t1);
}

__global__ void copy_k(const float4* __restrict__ in, float4* __restrict__ out) {
    int i = blockIdx.x * blockDim.x + threadIdx.x;
    out[i] = in[i];
}

// Task decode for phases 1/2: T -> (rr = T>>6, coQhi = (T>>5)&1,
// lane part: pA = (T>>1)&15, coQlo = T&1, coQ = coQhi*2+coQlo).
// A warp (32 consecutive T) shares rr and coQhi: act loads dedup to 16
// addresses (1 wf), weight loads to 2 addresses (1 wf per LDS.128).

// conv1 task: 8 acc pairs (4 co x 2 pp)
__device__ __forceinline__ void conv1_task(ull* su, int T) {
    int rr = T >> 6;
    int pA = (T >> 1) & 15, pB = pA + 16;
    int coQ = (((T >> 5) & 1) << 1) | (T & 1);
    int coB = coQ << 2;
    ull acc[8];
    #pragma unroll
    for (int i = 0; i < 8; i++) acc[i] = 0ull;
    #pragma unroll
    for (int dy = 0; dy < 3; dy++) {
        const ull* rp = su + SZU + (rr + dy) * PW + 1;
        #pragma unroll
        for (int dx = 0; dx < 3; dx++) {
            ull qa = rp[pA + dx - 1];
            ull qb = rp[pB + dx - 1];
            const ull* wp = su + WU0 + (dy * 3 + dx) * 16 + coB;
            ulonglong2 w01 = *(const ulonglong2*)(wp);
            ulonglong2 w23 = *(const ulonglong2*)(wp + 2);
            fma2(acc[0], w01.x, qa); fma2(acc[1], w01.x, qb);
            fma2(acc[2], w01.y, qa); fma2(acc[3], w01.y, qb);
            fma2(acc[4], w23.x, qa); fma2(acc[5], w23.x, qb);
            fma2(acc[6], w23.y, qa); fma2(acc[7], w23.y, qb);
        }
    }
    #pragma unroll
    for (int j = 0; j < 4; j++) {
        int co = coB + j;
        ull b2v = su[BFU + co];
        ull rA = xla_tanh2(acc[2*j],     b2v);
        ull rB = xla_tanh2(acc[2*j + 1], b2v);
        ull* op = su + S1U + (co * R1 + rr) * PW + 1;
        op[pA] = rA;
        op[pB] = rB;
        if (pA == 15) op[-1] = swap32(rB);   // halo = swap(pair 31)
        if (pA == 0)  op[32] = swap32(rA);   // halo = swap(pair 0)
    }
}

// conv2 task: 8 acc pairs (4 co x 2 pp), chain (dy,dx,ci)
__device__ __forceinline__ void conv2_task(ull* su, int T) {
    int rr = T >> 6;
    int pA = (T >> 1) & 15, pB = pA + 16;
    int coQ = (((T >> 5) & 1) << 1) | (T & 1);
    int coB = coQ << 2;
    ull acc[8];
    #pragma unroll
    for (int i = 0; i < 8; i++) acc[i] = 0ull;
    #pragma unroll
    for (int dy = 0; dy < 3; dy++) {
        const ull* rbp = su + S1U + (rr + dy) * PW + 1;
        #pragma unroll
        for (int dx = 0; dx < 3; dx++) {
            const ull* wb = su + WU1 + (dy * 3 + dx) * 256 + coB;
            #pragma unroll 8
            for (int ci = 0; ci < 16; ci++) {
                const ull* rp = rbp + ci * (R1 * PW);
                ull qa = rp[pA + dx - 1];
                ull qb = rp[pB + dx - 1];
                const ull* wp = wb + ci * 16;
                ulonglong2 w01 = *(const ulonglong2*)(wp);
                ulonglong2 w23 = *(const ulonglong2*)(wp + 2);
                fma2(acc[0], w01.x, qa); fma2(acc[1], w01.x, qb);
                fma2(acc[2], w01.y, qa); fma2(acc[3], w01.y, qb);
                fma2(acc[4], w23.x, qa); fma2(acc[5], w23.x, qb);
                fma2(acc[6], w23.y, qa); fma2(acc[7], w23.y, qb);
            }
        }
    }
    #pragma unroll
    for (int j = 0; j < 4; j++) {
        int co = coB + j;
        ull b2v = su[BFU + 16 + co];
        ull rA = xla_tanh2(acc[2*j],     b2v);
        ull rB = xla_tanh2(acc[2*j + 1], b2v);
        ull* op = su + S2U + (co * R2 + rr) * PW + 1;
        op[pA] = rA;
        op[pB] = rB;
        if (pA == 15) op[-1] = swap32(rB);
        if (pA == 0)  op[32] = swap32(rA);
    }
}

// One fused layer. All conv accumulations are single fp32 FMA chains from 0
// in k = (dy, dx, ci) order (ci fastest), bias after — bit-identical to XLA.
__global__ void __launch_bounds__(THREADS, 1)
layer_kernel(float* __restrict__ x,
             const float* __restrict__ w0, const float* __restrict__ b0,
             const float* __restrict__ w1, const float* __restrict__ b1,
             const float* __restrict__ w2, const float* __restrict__ b2,
             int parity)
{
    extern __shared__ ull su[];

    const int tid   = threadIdx.x;
    const int rbase = blockIdx.x * TH;                 // even
    const int xbase = ((int)blockIdx.y) << 12;         // b*4096

    // ---- Phase 0: weights as duplicated (w,w) pairs + packed biases + input ----
    for (int t = tid; t < 2304; t += THREADS) { float w = w1[t]; su[WU1 + t] = pk(w, w); }
    if (tid < 144) {
        float a = w0[tid], b = w2[tid];
        su[WU0 + tid] = pk(a, a);
        su[WU2 + tid] = pk(b, b);
    }
    if (tid >= 160 && tid < 176) { int i = tid - 160; float v = b0[i]; su[BFU + i] = pk(v, v); }
    if (tid >= 192 && tid < 208) { int i = tid - 192; float v = b1[i]; su[BFU + 16 + i] = pk(v, v); }
    if (tid == 224) { float v = b2[0]; su[BFU + 32] = pk(v, v); }

    // packed masked input: entry e of row rr holds pair p = e-1:
    // ( z[gr][p&63], z[gr][(p+32)&63] ), zeroed at non-A sites.
    for (int t = tid; t < RZ * PW; t += THREADS) {
        int rr = t / PW, e = t - rr * PW, p = e - 1;
        int gr = (rbase + rr - 3) & 63;
        int c0 = p & 63, c1 = (p + 32) & 63;
        const float* row = x + xbase + (gr << 6);
        float v0 = row[c0], v1 = row[c1];
        v0 = (((gr + c0) & 1) == parity) ? v0 : 0.0f;
        v1 = (((gr + c1) & 1) == parity) ? v1 : 0.0f;
        su[SZU + t] = pk(v0, v1);
    }
    __syncthreads();

    // ---- Phase 1: conv1 (1 -> 16): 1280 tasks = 2 slots x 640 threads ----
    conv1_task(su, tid);
    conv1_task(su, tid + 640);
    __syncthreads();

    // ---- Phase 2: conv2 (16 -> 16): 1152 tasks = 640 + 512 ----
    conv2_task(su, tid);
    if (tid < 512) conv2_task(su, tid + 640);
    __syncthreads();

    // ---- Phase 3: conv3 (16 -> 1), chain (dy,dx,ci), bias, STE sign update ----
    // 512 tasks: 16 rows x 32 pairs; pair p0 covers columns (p0, p0+32)
    if (tid < TH * 32) {
        int rr = tid >> 5;
        int p0 = tid & 31;
        ull acc = 0ull;
        #pragma unroll
        for (int dy = 0; dy < 3; dy++) {
            const ull* rbp = su + S2U + (rr + dy) * PW + 1;
            #pragma unroll
            for (int dx = 0; dx < 3; dx++) {
                const ull* wp = su + WU2 + (dy * 3 + dx) * 16;
                #pragma unroll 8
                for (int ci = 0; ci < 16; ci++) {
                    const ull* rp = rbp + ci * (R2 * PW);
                    fma2(acc, wp[ci], rp[p0 + dx - 1]);
                }
            }
        }
        float bb, dummy;
        upk(su[BFU + 32], bb, dummy);
        float u0, u1;
        upk(acc, u0, u1);
        float l0 = __fadd_rn(u0, bb);
        float l1 = __fadd_rn(u1, bb);
        int gr = rbase + rr;
        // columns p0 and p0+32 share parity -> uniform condition per thread
        if (((gr + p0) & 1) != parity) {
            float* row = x + xbase + (gr << 6);
            float s0 = (l0 > 0.0f) ? 1.0f : ((l0 < 0.0f) ? -1.0f : 0.0f);
            float s1v = (l1 > 0.0f) ? 1.0f : ((l1 < 0.0f) ? -1.0f : 0.0f);
            // STE forward exactly as XLA computes it: l + (sign(l) - l)
            float m0 = __fadd_rn(l0, __fadd_rn(s0, -l0));
            float m1 = __fadd_rn(l1, __fadd_rn(s1v, -l1));
            row[p0]      = __fmul_rn(row[p0],      m0);
            row[p0 + 32] = __fmul_rn(row[p0 + 32], m1);
        }
    }
}

extern "C" void kernel_launch(void* const* d_in, const int* in_sizes, int n_in,
                              void* d_out, int out_size)
{
    const float* z  = (const float*)d_in[0];
    const float* W0 = (const float*)d_in[1];
    const float* b0 = (const float*)d_in[2];
    const float* W1 = (const float*)d_in[3];
    const float* b1 = (const float*)d_in[4];
    const float* W2 = (const float*)d_in[5];
    const float* b2 = (const float*)d_in[6];
    float* x = (float*)d_out;

    cudaFuncSetAttribute(layer_kernel, cudaFuncAttributeMaxDynamicSharedMemorySize,
                         (int)SMEM_BYTES);

    // reset working state each replay: x <- z
    copy_k<<<(Bg * Lg * Lg) / (4 * 256), 256>>>((const float4*)z, (float4*)x);

    for (int i = 0; i < 4; i++) {
        layer_kernel<<<dim3(NTILES, Bg), THREADS, SMEM_BYTES>>>(
            x,
            W0 + i * 144, b0 + i * 16,
            W1 + i * 2304, b1 + i * 16,
            W2 + i * 144, b2 + i,
            i & 1);
    }
}

// round 10
// speedup vs baseline: 1.2195x; 1.0461x over previous
#include <cuda_runtime.h>

typedef unsigned long long ull;

#define Lg 64
#define Bg 1024
#define TH 16
#define NTILES (Lg/TH)          // 4
#define THREADS 640
#define R1 (TH+4)               // 20 conv1 output rows (halo 2)
#define R2 (TH+2)               // 18 conv2 output rows (halo 1)
#define RZ (TH+6)               // 22 input rows (halo 3)
#define PW 34                   // pairs per row: p = -1..32 (wrapped halo)

// ---- shared memory layout (ull units) ----
#define S1U 0                               // 16*20*34 = 10880
#define S2U (S1U + 16*R1*PW)                // 10880 (+9792)
#define SZU (S2U + 16*R2*PW)                // 20672 (+748)
#define WU1 (SZU + RZ*PW)                   // 21420 (2304)
#define WU0 (WU1 + 2304)                    // 23724 (144)
#define WU2 (WU0 + 144)                     // 23868 (144)
#define BFU (WU2 + 144)                     // 24012 (packed biases: 33 ull)
#define U_TOTAL (BFU + 33)                  // 24045
#define SMEM_BYTES ((size_t)U_TOTAL * 8)    // 192360 B

// ---- packed f32x2 helpers (sm_100+) : per-lane exact fp32 ops ----
__device__ __forceinline__ ull pk(float lo, float hi) {
    ull r; asm("mov.b64 %0, {%1, %2};" : "=l"(r) : "f"(lo), "f"(hi)); return r;
}
__device__ __forceinline__ void upk(ull v, float& lo, float& hi) {
    asm("mov.b64 {%0, %1}, %2;" : "=f"(lo), "=f"(hi) : "l"(v));
}
__device__ __forceinline__ void fma2(ull& d, ull a, ull b) {   // d += a*b
    asm("fma.rn.f32x2 %0, %1, %2, %0;" : "+l"(d) : "l"(a), "l"(b));
}
__device__ __forceinline__ void fma2h(ull& d, ull a, ull c) {  // d = d*a + c
    asm("fma.rn.f32x2 %0, %0, %1, %2;" : "+l"(d) : "l"(a), "l"(c));
}
__device__ __forceinline__ ull add2(ull a, ull b) {
    ull r; asm("add.rn.f32x2 %0, %1, %2;" : "=l"(r) : "l"(a), "l"(b)); return r;
}
__device__ __forceinline__ ull mul2(ull a, ull b) {
    ull r; asm("mul.rn.f32x2 %0, %1, %2;" : "=l"(r) : "l"(a), "l"(b)); return r;
}
__device__ __forceinline__ ull dup(float f) { return pk(f, f); }
__device__ __forceinline__ ull swap32(ull v) { return (v >> 32) | (v << 32); }

// Packed XLA EmitFastTanh on an accumulator pair + packed bias.
// Per-lane op sequence identical to the verified scalar replica.
// DO NOT CHANGE the op sequence (bit-exactness vs XLA verified).
__device__ __forceinline__ ull xla_tanh2(ull acc, ull bias2) {
    ull s = add2(acc, bias2);
    float s0, s1; upk(s, s0, s1);
    float xc0 = fminf(fmaxf(s0, -9.0f), 9.0f);
    float xc1 = fminf(fmaxf(s1, -9.0f), 9.0f);
    ull xc = pk(xc0, xc1);
    ull x2 = mul2(xc, xc);
    ull p = dup(-2.76076847742355e-16f);
    fma2h(p, x2, dup( 2.00018790482477e-13f));
    fma2h(p, x2, dup(-8.60467152213735e-11f));
    fma2h(p, x2, dup( 5.12229709037114e-08f));
    fma2h(p, x2, dup( 1.48572235717979e-05f));
    fma2h(p, x2, dup( 6.37261928875436e-04f));
    fma2h(p, x2, dup( 4.89352455891786e-03f));
    ull num = mul2(xc, p);
    ull q = dup(1.19825839466702e-06f);
    fma2h(q, x2, dup(1.18534705686654e-04f));
    fma2h(q, x2, dup(2.26843463243900e-03f));
    fma2h(q, x2, dup(4.89352518554385e-03f));
    float n0, n1, q0, q1;
    upk(num, n0, n1); upk(q, q0, q1);
    float r0 = __fdiv_rn(n0, q0);
    float r1 = __fdiv_rn(n1, q1);
    float t0 = (fabsf(s0) < 0.0004f) ? s0 : r0;
    float t1 = (fabsf(s1) < 0.0004f) ? s1 : r1;
    return pk(t0, t1);
}

__global__ void copy_k(const float4* __restrict__ in, float4* __restrict__ out) {
    int i = blockIdx.x * blockDim.x + threadIdx.x;
    out[i] = in[i];
}

// conv1 task: 8 acc pairs (4 co x 2 pp), chain (dy,dx)
__device__ __forceinline__ void conv1_task(ull* su, int T) {
    int rr = T >> 6;
    int pA = (T >> 1) & 15, pB = pA + 16;
    int coQ = (((T >> 5) & 1) << 1) | (T & 1);
    int coB = coQ << 2;
    ull acc[8];
    #pragma unroll
    for (int i = 0; i < 8; i++) acc[i] = 0ull;
    #pragma unroll
    for (int dy = 0; dy < 3; dy++) {
        const ull* rp = su + SZU + (rr + dy) * PW + 1;
        #pragma unroll
        for (int dx = 0; dx < 3; dx++) {
            ull qa = rp[pA + dx - 1];
            ull qb = rp[pB + dx - 1];
            const ull* wp = su + WU0 + (dy * 3 + dx) * 16 + coB;
            ulonglong2 w01 = *(const ulonglong2*)(wp);
            ulonglong2 w23 = *(const ulonglong2*)(wp + 2);
            fma2(acc[0], w01.x, qa); fma2(acc[1], w01.x, qb);
            fma2(acc[2], w01.y, qa); fma2(acc[3], w01.y, qb);
            fma2(acc[4], w23.x, qa); fma2(acc[5], w23.x, qb);
            fma2(acc[6], w23.y, qa); fma2(acc[7], w23.y, qb);
        }
    }
    #pragma unroll
    for (int j = 0; j < 4; j++) {
        int co = coB + j;
        ull b2v = su[BFU + co];
        ull rA = xla_tanh2(acc[2*j],     b2v);
        ull rB = xla_tanh2(acc[2*j + 1], b2v);
        ull* op = su + S1U + (co * R1 + rr) * PW + 1;
        op[pA] = rA;
        op[pB] = rB;
        if (pA == 15) op[-1] = swap32(rB);   // halo = swap(pair 31)
        if (pA == 0)  op[32] = swap32(rA);   // halo = swap(pair 0)
    }
}

// conv2 task: 8 acc pairs (4 co x 2 pp), chain (dy,dx,ci),
// ci-loop manually software-pipelined (prefetch depth 1).
__device__ __forceinline__ void conv2_task(ull* su, int T) {
    int rr = T >> 6;
    int pA = (T >> 1) & 15, pB = pA + 16;
    int coQ = (((T >> 5) & 1) << 1) | (T & 1);
    int coB = coQ << 2;
    ull acc[8];
    #pragma unroll
    for (int i = 0; i < 8; i++) acc[i] = 0ull;
    #pragma unroll
    for (int dy = 0; dy < 3; dy++) {
        const ull* rbp = su + S1U + (rr + dy) * PW + 1;
        #pragma unroll
        for (int dx = 0; dx < 3; dx++) {
            const ull* wb = su + WU1 + (dy * 3 + dx) * 256 + coB;
            // pipeline prologue: ci = 0
            ull qa = rbp[pA + dx - 1];
            ull qb = rbp[pB + dx - 1];
            ulonglong2 w01 = *(const ulonglong2*)(wb);
            ulonglong2 w23 = *(const ulonglong2*)(wb + 2);
            #pragma unroll
            for (int ci = 0; ci < 16; ci++) {
                ull nqa = qa, nqb = qb;
                ulonglong2 nw01 = w01, nw23 = w23;
                if (ci < 15) {                      // prefetch ci+1
                    const ull* rp = rbp + (ci + 1) * (R1 * PW);
                    nqa = rp[pA + dx - 1];
                    nqb = rp[pB + dx - 1];
                    const ull* wp = wb + (ci + 1) * 16;
                    nw01 = *(const ulonglong2*)(wp);
                    nw23 = *(const ulonglong2*)(wp + 2);
                }
                fma2(acc[0], w01.x, qa); fma2(acc[1], w01.x, qb);
                fma2(acc[2], w01.y, qa); fma2(acc[3], w01.y, qb);
                fma2(acc[4], w23.x, qa); fma2(acc[5], w23.x, qb);
                fma2(acc[6], w23.y, qa); fma2(acc[7], w23.y, qb);
                qa = nqa; qb = nqb; w01 = nw01; w23 = nw23;
            }
        }
    }
    #pragma unroll
    for (int j = 0; j < 4; j++) {
        int co = coB + j;
        ull b2v = su[BFU + 16 + co];
        ull rA = xla_tanh2(acc[2*j],     b2v);
        ull rB = xla_tanh2(acc[2*j + 1], b2v);
        ull* op = su + S2U + (co * R2 + rr) * PW + 1;
        op[pA] = rA;
        op[pB] = rB;
        if (pA == 15) op[-1] = swap32(rB);
        if (pA == 0)  op[32] = swap32(rA);
    }
}

// One fused layer. All conv accumulations are single fp32 FMA chains from 0
// in k = (dy, dx, ci) order (ci fastest), bias after — bit-identical to XLA.
__global__ void __launch_bounds__(THREADS, 1)
layer_kernel(float* __restrict__ x,
             const float* __restrict__ w0, const float* __restrict__ b0,
             const float* __restrict__ w1, const float* __restrict__ b1,
             const float* __restrict__ w2, const float* __restrict__ b2,
             int parity)
{
    extern __shared__ ull su[];

    const int tid   = threadIdx.x;
    const int rbase = blockIdx.x * TH;                 // even
    const int xbase = ((int)blockIdx.y) << 12;         // b*4096

    // ---- Phase 0: weights as duplicated (w,w) pairs + packed biases + input ----
    for (int t = tid; t < 2304; t += THREADS) { float w = w1[t]; su[WU1 + t] = pk(w, w); }
    if (tid < 144) {
        float a = w0[tid], b = w2[tid];
        su[WU0 + tid] = pk(a, a);
        su[WU2 + tid] = pk(b, b);
    }
    if (tid >= 160 && tid < 176) { int i = tid - 160; float v = b0[i]; su[BFU + i] = pk(v, v); }
    if (tid >= 192 && tid < 208) { int i = tid - 192; float v = b1[i]; su[BFU + 16 + i] = pk(v, v); }
    if (tid == 224) { float v = b2[0]; su[BFU + 32] = pk(v, v); }

    // packed masked input: entry e of row rr holds pair p = e-1:
    // ( z[gr][p&63], z[gr][(p+32)&63] ), zeroed at non-A sites.
    for (int t = tid; t < RZ * PW; t += THREADS) {
        int rr = t / PW, e = t - rr * PW, p = e - 1;
        int gr = (rbase + rr - 3) & 63;
        int c0 = p & 63, c1 = (p + 32) & 63;
        const float* row = x + xbase + (gr << 6);
        float v0 = row[c0], v1 = row[c1];
        v0 = (((gr + c0) & 1) == parity) ? v0 : 0.0f;
        v1 = (((gr + c1) & 1) == parity) ? v1 : 0.0f;
        su[SZU + t] = pk(v0, v1);
    }
    __syncthreads();

    // ---- Phase 1: conv1 (1 -> 16): 1280 tasks = 2 slots x 640 threads ----
    #pragma unroll 1
    for (int s = 0; s < 1280; s += THREADS)
        conv1_task(su, tid + s);
    __syncthreads();

    // ---- Phase 2: conv2 (16 -> 16): 1152 tasks = 640 + 512 ----
    #pragma unroll 1
    for (int s = 0; s < 1152; s += THREADS) {
        int T = tid + s;
        if (T < 1152) conv2_task(su, T);
    }
    __syncthreads();

    // ---- Phase 3: conv3 (16 -> 1), chain (dy,dx,ci), bias, STE sign update ----
    // 512 tasks: 16 rows x 32 pairs; pair p0 covers columns (p0, p0+32)
    if (tid < TH * 32) {
        int rr = tid >> 5;
        int p0 = tid & 31;
        ull acc = 0ull;
        #pragma unroll
        for (int dy = 0; dy < 3; dy++) {
            const ull* rbp = su + S2U + (rr + dy) * PW + 1;
            #pragma unroll
            for (int dx = 0; dx < 3; dx++) {
                const ull* wp = su + WU2 + (dy * 3 + dx) * 16;
                // manual 1-deep pipeline
                ull qa = rbp[p0 + dx - 1];
                ull wv = wp[0];
                #pragma unroll
                for (int ci = 0; ci < 16; ci++) {
                    ull nqa = qa, nwv = wv;
                    if (ci < 15) {
                        nqa = rbp[(ci + 1) * (R2 * PW) + p0 + dx - 1];
                        nwv = wp[ci + 1];
                    }
                    fma2(acc, wv, qa);
                    qa = nqa; wv = nwv;
                }
            }
        }
        float bb, dummy;
        upk(su[BFU + 32], bb, dummy);
        float u0, u1;
        upk(acc, u0, u1);
        float l0 = __fadd_rn(u0, bb);
        float l1 = __fadd_rn(u1, bb);
        int gr = rbase + rr;
        // columns p0 and p0+32 share parity -> uniform condition per thread
        if (((gr + p0) & 1) != parity) {
            float* row = x + xbase + (gr << 6);
            float s0 = (l0 > 0.0f) ? 1.0f : ((l0 < 0.0f) ? -1.0f : 0.0f);
            float s1v = (l1 > 0.0f) ? 1.0f : ((l1 < 0.0f) ? -1.0f : 0.0f);
            // STE forward exactly as XLA computes it: l + (sign(l) - l)
            float m0 = __fadd_rn(l0, __fadd_rn(s0, -l0));
            float m1 = __fadd_rn(l1, __fadd_rn(s1v, -l1));
            row[p0]      = __fmul_rn(row[p0],      m0);
            row[p0 + 32] = __fmul_rn(row[p0 + 32], m1);
        }
    }
}

extern "C" void kernel_launch(void* const* d_in, const int* in_sizes, int n_in,
                              void* d_out, int out_size)
{
    const float* z  = (const float*)d_in[0];
    const float* W0 = (const float*)d_in[1];
    const float* b0 = (const float*)d_in[2];
    const float* W1 = (const float*)d_in[3];
    const float* b1 = (const float*)d_in[4];
    const float* W2 = (const float*)d_in[5];
    const float* b2 = (const float*)d_in[6];
    float* x = (float*)d_out;

    cudaFuncSetAttribute(layer_kernel, cudaFuncAttributeMaxDynamicSharedMemorySize,
                         (int)SMEM_BYTES);

    // reset working state each replay: x <- z
    copy_k<<<(Bg * Lg * Lg) / (4 * 256), 256>>>((const float4*)z, (float4*)x);

    for (int i = 0; i < 4; i++) {
        layer_kernel<<<dim3(NTILES, Bg), THREADS, SMEM_BYTES>>>(
            x,
            W0 + i * 144, b0 + i * 16,
            W1 + i * 2304, b1 + i * 16,
            W2 + i * 144, b2 + i,
            i & 1);
    }
}

// round 11
// speedup vs baseline: 1.2242x; 1.0038x over previous
#include <cuda_runtime.h>

typedef unsigned long long ull;

#define Lg 64
#define Bg 1024
#define TH 16
#define NTILES (Lg/TH)          // 4
#define THREADS 768
#define R1 (TH+4)               // 20 conv1 output rows (halo 2)
#define R2 (TH+2)               // 18 conv2 output rows (halo 1)
#define RZ (TH+6)               // 22 input rows (halo 3)
#define PW 34                   // pairs per row: p = -1..32 (wrapped halo)

// ---- shared memory layout (ull units) ----
#define S1U 0                               // 16*20*34 = 10880
#define S2U (S1U + 16*R1*PW)                // 10880 (+9792)
#define SZU (S2U + 16*R2*PW)                // 20672 (+748)
#define WU1 (SZU + RZ*PW)                   // 21420 (2304)
#define WU0 (WU1 + 2304)                    // 23724 (144)
#define WU2 (WU0 + 144)                     // 23868 (144)
#define BFU (WU2 + 144)                     // 24012 (packed biases: 33 ull)
#define U_TOTAL (BFU + 33)                  // 24045
#define SMEM_BYTES ((size_t)U_TOTAL * 8)    // 192360 B

// ---- packed f32x2 helpers (sm_100+) : per-lane exact fp32 ops ----
__device__ __forceinline__ ull pk(float lo, float hi) {
    ull r; asm("mov.b64 %0, {%1, %2};" : "=l"(r) : "f"(lo), "f"(hi)); return r;
}
__device__ __forceinline__ void upk(ull v, float& lo, float& hi) {
    asm("mov.b64 {%0, %1}, %2;" : "=f"(lo), "=f"(hi) : "l"(v));
}
__device__ __forceinline__ void fma2(ull& d, ull a, ull b) {   // d += a*b
    asm("fma.rn.f32x2 %0, %1, %2, %0;" : "+l"(d) : "l"(a), "l"(b));
}
__device__ __forceinline__ void fma2h(ull& d, ull a, ull c) {  // d = d*a + c
    asm("fma.rn.f32x2 %0, %0, %1, %2;" : "+l"(d) : "l"(a), "l"(c));
}
__device__ __forceinline__ ull add2(ull a, ull b) {
    ull r; asm("add.rn.f32x2 %0, %1, %2;" : "=l"(r) : "l"(a), "l"(b)); return r;
}
__device__ __forceinline__ ull mul2(ull a, ull b) {
    ull r; asm("mul.rn.f32x2 %0, %1, %2;" : "=l"(r) : "l"(a), "l"(b)); return r;
}
__device__ __forceinline__ ull dup(float f) { return pk(f, f); }
__device__ __forceinline__ ull swap32(ull v) { return (v >> 32) | (v << 32); }

// Packed XLA EmitFastTanh on an accumulator pair + packed bias.
// Per-lane op sequence identical to the verified scalar replica.
// DO NOT CHANGE the op sequence (bit-exactness vs XLA verified).
__device__ __forceinline__ ull xla_tanh2(ull acc, ull bias2) {
    ull s = add2(acc, bias2);
    float s0, s1; upk(s, s0, s1);
    float xc0 = fminf(fmaxf(s0, -9.0f), 9.0f);
    float xc1 = fminf(fmaxf(s1, -9.0f), 9.0f);
    ull xc = pk(xc0, xc1);
    ull x2 = mul2(xc, xc);
    ull p = dup(-2.76076847742355e-16f);
    fma2h(p, x2, dup( 2.00018790482477e-13f));
    fma2h(p, x2, dup(-8.60467152213735e-11f));
    fma2h(p, x2, dup( 5.12229709037114e-08f));
    fma2h(p, x2, dup( 1.48572235717979e-05f));
    fma2h(p, x2, dup( 6.37261928875436e-04f));
    fma2h(p, x2, dup( 4.89352455891786e-03f));
    ull num = mul2(xc, p);
    ull q = dup(1.19825839466702e-06f);
    fma2h(q, x2, dup(1.18534705686654e-04f));
    fma2h(q, x2, dup(2.26843463243900e-03f));
    fma2h(q, x2, dup(4.89352518554385e-03f));
    float n0, n1, q0, q1;
    upk(num, n0, n1); upk(q, q0, q1);
    float r0 = __fdiv_rn(n0, q0);
    float r1 = __fdiv_rn(n1, q1);
    float t0 = (fabsf(s0) < 0.0004f) ? s0 : r0;
    float t1 = (fabsf(s1) < 0.0004f) ? s1 : r1;
    return pk(t0, t1);
}

__global__ void copy_k(const float4* __restrict__ in, float4* __restrict__ out) {
    int i = blockIdx.x * blockDim.x + threadIdx.x;
    out[i] = in[i];
}

// conv1 task: 8 acc pairs (4 co x 2 pp), chain (dy,dx)
__device__ __forceinline__ void conv1_task(ull* su, int T) {
    int rr = T >> 6;
    int pA = (T >> 1) & 15, pB = pA + 16;
    int coQ = (((T >> 5) & 1) << 1) | (T & 1);
    int coB = coQ << 2;
    ull acc[8];
    #pragma unroll
    for (int i = 0; i < 8; i++) acc[i] = 0ull;
    #pragma unroll
    for (int dy = 0; dy < 3; dy++) {
        const ull* rp = su + SZU + (rr + dy) * PW + 1;
        #pragma unroll
        for (int dx = 0; dx < 3; dx++) {
            ull qa = rp[pA + dx - 1];
            ull qb = rp[pB + dx - 1];
            const ull* wp = su + WU0 + (dy * 3 + dx) * 16 + coB;
            ulonglong2 w01 = *(const ulonglong2*)(wp);
            ulonglong2 w23 = *(const ulonglong2*)(wp + 2);
            fma2(acc[0], w01.x, qa); fma2(acc[1], w01.x, qb);
            fma2(acc[2], w01.y, qa); fma2(acc[3], w01.y, qb);
            fma2(acc[4], w23.x, qa); fma2(acc[5], w23.x, qb);
            fma2(acc[6], w23.y, qa); fma2(acc[7], w23.y, qb);
        }
    }
    #pragma unroll
    for (int j = 0; j < 4; j++) {
        int co = coB + j;
        ull b2v = su[BFU + co];
        ull rA = xla_tanh2(acc[2*j],     b2v);
        ull rB = xla_tanh2(acc[2*j + 1], b2v);
        ull* op = su + S1U + (co * R1 + rr) * PW + 1;
        op[pA] = rA;
        op[pB] = rB;
        if (pA == 15) op[-1] = swap32(rB);   // halo = swap(pair 31)
        if (pA == 0)  op[32] = swap32(rA);   // halo = swap(pair 0)
    }
}

// conv2 task: 8 acc pairs (4 co x 2 pp), chain (dy,dx,ci),
// ci-loop manually software-pipelined (prefetch depth 1).
__device__ __forceinline__ void conv2_task(ull* su, int T) {
    int rr = T >> 6;
    int pA = (T >> 1) & 15, pB = pA + 16;
    int coQ = (((T >> 5) & 1) << 1) | (T & 1);
    int coB = coQ << 2;
    ull acc[8];
    #pragma unroll
    for (int i = 0; i < 8; i++) acc[i] = 0ull;
    #pragma unroll
    for (int dy = 0; dy < 3; dy++) {
        const ull* rbp = su + S1U + (rr + dy) * PW + 1;
        #pragma unroll
        for (int dx = 0; dx < 3; dx++) {
            const ull* wb = su + WU1 + (dy * 3 + dx) * 256 + coB;
            // pipeline prologue: ci = 0
            ull qa = rbp[pA + dx - 1];
            ull qb = rbp[pB + dx - 1];
            ulonglong2 w01 = *(const ulonglong2*)(wb);
            ulonglong2 w23 = *(const ulonglong2*)(wb + 2);
            #pragma unroll
            for (int ci = 0; ci < 16; ci++) {
                ull nqa = qa, nqb = qb;
                ulonglong2 nw01 = w01, nw23 = w23;
                if (ci < 15) {                      // prefetch ci+1
                    const ull* rp = rbp + (ci + 1) * (R1 * PW);
                    nqa = rp[pA + dx - 1];
                    nqb = rp[pB + dx - 1];
                    const ull* wp = wb + (ci + 1) * 16;
                    nw01 = *(const ulonglong2*)(wp);
                    nw23 = *(const ulonglong2*)(wp + 2);
                }
                fma2(acc[0], w01.x, qa); fma2(acc[1], w01.x, qb);
                fma2(acc[2], w01.y, qa); fma2(acc[3], w01.y, qb);
                fma2(acc[4], w23.x, qa); fma2(acc[5], w23.x, qb);
                fma2(acc[6], w23.y, qa); fma2(acc[7], w23.y, qb);
                qa = nqa; qb = nqb; w01 = nw01; w23 = nw23;
            }
        }
    }
    #pragma unroll
    for (int j = 0; j < 4; j++) {
        int co = coB + j;
        ull b2v = su[BFU + 16 + co];
        ull rA = xla_tanh2(acc[2*j],     b2v);
        ull rB = xla_tanh2(acc[2*j + 1], b2v);
        ull* op = su + S2U + (co * R2 + rr) * PW + 1;
        op[pA] = rA;
        op[pB] = rB;
        if (pA == 15) op[-1] = swap32(rB);
        if (pA == 0)  op[32] = swap32(rA);
    }
}

// One fused layer. All conv accumulations are single fp32 FMA chains from 0
// in k = (dy, dx, ci) order (ci fastest), bias after — bit-identical to XLA.
__global__ void __launch_bounds__(THREADS, 1)
layer_kernel(float* __restrict__ x,
             const float* __restrict__ w0, const float* __restrict__ b0,
             const float* __restrict__ w1, const float* __restrict__ b1,
             const float* __restrict__ w2, const float* __restrict__ b2,
             int parity)
{
    extern __shared__ ull su[];

    const int tid   = threadIdx.x;
    const int rbase = blockIdx.x * TH;                 // even
    const int xbase = ((int)blockIdx.y) << 12;         // b*4096

    // ---- Phase 0: weights as duplicated (w,w) pairs + packed biases + input ----
    for (int t = tid; t < 2304; t += THREADS) { float w = w1[t]; su[WU1 + t] = pk(w, w); }
    if (tid < 144) {
        float a = w0[tid], b = w2[tid];
        su[WU0 + tid] = pk(a, a);
        su[WU2 + tid] = pk(b, b);
    }
    if (tid >= 160 && tid < 176) { int i = tid - 160; float v = b0[i]; su[BFU + i] = pk(v, v); }
    if (tid >= 192 && tid < 208) { int i = tid - 192; float v = b1[i]; su[BFU + 16 + i] = pk(v, v); }
    if (tid == 224) { float v = b2[0]; su[BFU + 32] = pk(v, v); }

    // packed masked input: entry e of row rr holds pair p = e-1:
    // ( z[gr][p&63], z[gr][(p+32)&63] ), zeroed at non-A sites.
    if (tid < RZ * PW) {
        int rr = tid / PW, e = tid - rr * PW, p = e - 1;
        int gr = (rbase + rr - 3) & 63;
        int c0 = p & 63, c1 = (p + 32) & 63;
        const float* row = x + xbase + (gr << 6);
        float v0 = row[c0], v1 = row[c1];
        v0 = (((gr + c0) & 1) == parity) ? v0 : 0.0f;
        v1 = (((gr + c1) & 1) == parity) ? v1 : 0.0f;
        su[SZU + tid] = pk(v0, v1);
    }
    __syncthreads();

    // ---- Phase 1: conv1 (1 -> 16): 1280 tasks = 768 + 512 ----
    #pragma unroll 1
    for (int s = 0; s < 1280; s += THREADS) {
        int T = tid + s;
        if (T < 1280) conv1_task(su, T);
    }
    __syncthreads();

    // ---- Phase 2: conv2 (16 -> 16): 1152 tasks = 768 + 384 ----
    #pragma unroll 1
    for (int s = 0; s < 1152; s += THREADS) {
        int T = tid + s;
        if (T < 1152) conv2_task(su, T);
    }
    __syncthreads();

    // ---- Phase 3: conv3 (16 -> 1), chain (dy,dx,ci), bias, STE sign update ----
    // 512 tasks: 16 rows x 32 pairs; pair p0 covers columns (p0, p0+32)
    if (tid < TH * 32) {
        int rr = tid >> 5;
        int p0 = tid & 31;
        ull acc = 0ull;
        #pragma unroll
        for (int dy = 0; dy < 3; dy++) {
            const ull* rbp = su + S2U + (rr + dy) * PW + 1;
            #pragma unroll
            for (int dx = 0; dx < 3; dx++) {
                const ull* wp = su + WU2 + (dy * 3 + dx) * 16;
                // manual 1-deep pipeline
                ull qa = rbp[p0 + dx - 1];
                ull wv = wp[0];
                #pragma unroll
                for (int ci = 0; ci < 16; ci++) {
                    ull nqa = qa, nwv = wv;
                    if (ci < 15) {
                        nqa = rbp[(ci + 1) * (R2 * PW) + p0 + dx - 1];
                        nwv = wp[ci + 1];
                    }
                    fma2(acc, wv, qa);
                    qa = nqa; wv = nwv;
                }
            }
        }
        float bb, dummy;
        upk(su[BFU + 32], bb, dummy);
        float u0, u1;
        upk(acc, u0, u1);
        float l0 = __fadd_rn(u0, bb);
        float l1 = __fadd_rn(u1, bb);
        int gr = rbase + rr;
        // columns p0 and p0+32 share parity -> uniform condition per thread
        if (((gr + p0) & 1) != parity) {
            float* row = x + xbase + (gr << 6);
            float s0 = (l0 > 0.0f) ? 1.0f : ((l0 < 0.0f) ? -1.0f : 0.0f);
            float s1v = (l1 > 0.0f) ? 1.0f : ((l1 < 0.0f) ? -1.0f : 0.0f);
            // STE forward exactly as XLA computes it: l + (sign(l) - l)
            float m0 = __fadd_rn(l0, __fadd_rn(s0, -l0));
            float m1 = __fadd_rn(l1, __fadd_rn(s1v, -l1));
            row[p0]      = __fmul_rn(row[p0],      m0);
            row[p0 + 32] = __fmul_rn(row[p0 + 32], m1);
        }
    }
}

extern "C" void kernel_launch(void* const* d_in, const int* in_sizes, int n_in,
                              void* d_out, int out_size)
{
    const float* z  = (const float*)d_in[0];
    const float* W0 = (const float*)d_in[1];
    const float* b0 = (const float*)d_in[2];
    const float* W1 = (const float*)d_in[3];
    const float* b1 = (const float*)d_in[4];
    const float* W2 = (const float*)d_in[5];
    const float* b2 = (const float*)d_in[6];
    float* x = (float*)d_out;

    cudaFuncSetAttribute(layer_kernel, cudaFuncAttributeMaxDynamicSharedMemorySize,
                         (int)SMEM_BYTES);

    // reset working state each replay: x <- z
    copy_k<<<(Bg * Lg * Lg) / (4 * 256), 256>>>((const float4*)z, (float4*)x);

    for (int i = 0; i < 4; i++) {
        layer_kernel<<<dim3(NTILES, Bg), THREADS, SMEM_BYTES>>>(
            x,
            W0 + i * 144, b0 + i * 16,
            W1 + i * 2304, b1 + i * 16,
            W2 + i * 144, b2 + i,
            i & 1);
    }
}

// round 12
// speedup vs baseline: 1.2245x; 1.0003x over previous
#include <cuda_runtime.h>

typedef unsigned long long ull;

#define Lg 64
#define Bg 1024
#define TH 16
#define NTILES (Lg/TH)          // 4
#define THREADS 640
#define R1 (TH+4)               // 20 conv1 output rows (halo 2)
#define R2 (TH+2)               // 18 conv2 output rows (halo 1)
#define RZ (TH+6)               // 22 input rows (halo 3)
#define PW 34                   // pairs per row: p = -1..32 (wrapped halo)

// ---- shared memory layout (ull units) ----
#define S1U 0                               // 16*20*34 = 10880
#define S2U (S1U + 16*R1*PW)                // 10880 (+9792)
#define SZU (S2U + 16*R2*PW)                // 20672 (+748)
#define WU1 (SZU + RZ*PW)                   // 21420 (2304)
#define WU0 (WU1 + 2304)                    // 23724 (144)
#define WU2 (WU0 + 144)                     // 23868 (144)
#define BFU (WU2 + 144)                     // 24012 (packed biases: 33 ull)
#define U_TOTAL (BFU + 33)                  // 24045
#define SMEM_BYTES ((size_t)U_TOTAL * 8)    // 192360 B

// ---- packed f32x2 helpers (sm_100+) : per-lane exact fp32 ops ----
__device__ __forceinline__ ull pk(float lo, float hi) {
    ull r; asm("mov.b64 %0, {%1, %2};" : "=l"(r) : "f"(lo), "f"(hi)); return r;
}
__device__ __forceinline__ void upk(ull v, float& lo, float& hi) {
    asm("mov.b64 {%0, %1}, %2;" : "=f"(lo), "=f"(hi) : "l"(v));
}
__device__ __forceinline__ void fma2(ull& d, ull a, ull b) {   // d += a*b
    asm("fma.rn.f32x2 %0, %1, %2, %0;" : "+l"(d) : "l"(a), "l"(b));
}
__device__ __forceinline__ void fma2h(ull& d, ull a, ull c) {  // d = d*a + c
    asm("fma.rn.f32x2 %0, %0, %1, %2;" : "+l"(d) : "l"(a), "l"(c));
}
__device__ __forceinline__ ull add2(ull a, ull b) {
    ull r; asm("add.rn.f32x2 %0, %1, %2;" : "=l"(r) : "l"(a), "l"(b)); return r;
}
__device__ __forceinline__ ull mul2(ull a, ull b) {
    ull r; asm("mul.rn.f32x2 %0, %1, %2;" : "=l"(r) : "l"(a), "l"(b)); return r;
}
__device__ __forceinline__ ull dup(float f) { return pk(f, f); }
__device__ __forceinline__ ull swap32(ull v) { return (v >> 32) | (v << 32); }

// Packed XLA EmitFastTanh on an accumulator pair + packed bias.
// Per-lane op sequence identical to the verified scalar replica.
// DO NOT CHANGE the op sequence (bit-exactness vs XLA verified).
__device__ __forceinline__ ull xla_tanh2(ull acc, ull bias2) {
    ull s = add2(acc, bias2);
    float s0, s1; upk(s, s0, s1);
    float xc0 = fminf(fmaxf(s0, -9.0f), 9.0f);
    float xc1 = fminf(fmaxf(s1, -9.0f), 9.0f);
    ull xc = pk(xc0, xc1);
    ull x2 = mul2(xc, xc);
    ull p = dup(-2.76076847742355e-16f);
    fma2h(p, x2, dup( 2.00018790482477e-13f));
    fma2h(p, x2, dup(-8.60467152213735e-11f));
    fma2h(p, x2, dup( 5.12229709037114e-08f));
    fma2h(p, x2, dup( 1.48572235717979e-05f));
    fma2h(p, x2, dup( 6.37261928875436e-04f));
    fma2h(p, x2, dup( 4.89352455891786e-03f));
    ull num = mul2(xc, p);
    ull q = dup(1.19825839466702e-06f);
    fma2h(q, x2, dup(1.18534705686654e-04f));
    fma2h(q, x2, dup(2.26843463243900e-03f));
    fma2h(q, x2, dup(4.89352518554385e-03f));
    float n0, n1, q0, q1;
    upk(num, n0, n1); upk(q, q0, q1);
    float r0 = __fdiv_rn(n0, q0);
    float r1 = __fdiv_rn(n1, q1);
    float t0 = (fabsf(s0) < 0.0004f) ? s0 : r0;
    float t1 = (fabsf(s1) < 0.0004f) ? s1 : r1;
    return pk(t0, t1);
}

__global__ void copy_k(const float4* __restrict__ in, float4* __restrict__ out) {
    int i = blockIdx.x * blockDim.x + threadIdx.x;
    out[i] = in[i];
}

// Task decode (phases 1/2): T -> rr = T>>5 (warp-uniform),
// p0 = (T>>2)&7 (pair base; pairs p0, p0+8, p0+16, p0+24), coQ = T&3.
// 4pp x 4co = 16 acc pairs; acts amortize over 4 co, weights over 4 pp:
// per (dy,dx,ci) iter: 4 act LDS.64 + 2 weight LDS.128 per 16 FMA2.

// conv1 task: chain (dy,dx)
__device__ __forceinline__ void conv1_task(ull* su, int T) {
    int rr = T >> 5;
    int p0 = (T >> 2) & 7;
    int coB = (T & 3) << 2;
    ull acc[16];
    #pragma unroll
    for (int i = 0; i < 16; i++) acc[i] = 0ull;
    #pragma unroll
    for (int dy = 0; dy < 3; dy++) {
        const ull* rp = su + SZU + (rr + dy) * PW + 1;
        #pragma unroll
        for (int dx = 0; dx < 3; dx++) {
            const ull* wp = su + WU0 + (dy * 3 + dx) * 16 + coB;
            ulonglong2 w01 = *(const ulonglong2*)(wp);
            ulonglong2 w23 = *(const ulonglong2*)(wp + 2);
            #pragma unroll
            for (int k = 0; k < 4; k++) {
                ull q = rp[p0 + 8 * k + dx - 1];
                fma2(acc[4*k + 0], w01.x, q);
                fma2(acc[4*k + 1], w01.y, q);
                fma2(acc[4*k + 2], w23.x, q);
                fma2(acc[4*k + 3], w23.y, q);
            }
        }
    }
    #pragma unroll
    for (int j = 0; j < 4; j++) {
        int co = coB + j;
        ull b2v = su[BFU + co];
        ull* op = su + S1U + (co * R1 + rr) * PW + 1;
        #pragma unroll
        for (int k = 0; k < 4; k++) {
            ull r = xla_tanh2(acc[4*k + j], b2v);
            op[p0 + 8 * k] = r;
            if (k == 3 && p0 == 7) op[-1] = swap32(r);  // halo = swap(pair 31)
            if (k == 0 && p0 == 0) op[32] = swap32(r);  // halo = swap(pair 0)
        }
    }
}

// conv2 task: chain (dy,dx,ci), ci-loop manually pipelined (depth 1)
__device__ __forceinline__ void conv2_task(ull* su, int T) {
    int rr = T >> 5;
    int p0 = (T >> 2) & 7;
    int coB = (T & 3) << 2;
    ull acc[16];
    #pragma unroll
    for (int i = 0; i < 16; i++) acc[i] = 0ull;
    #pragma unroll
    for (int dy = 0; dy < 3; dy++) {
        const ull* rbp = su + S1U + (rr + dy) * PW + 1;
        #pragma unroll
        for (int dx = 0; dx < 3; dx++) {
            const ull* wb = su + WU1 + (dy * 3 + dx) * 256 + coB;
            // pipeline prologue: ci = 0
            ull q0v = rbp[p0 + dx - 1];
            ull q1v = rbp[p0 + 8 + dx - 1];
            ull q2v = rbp[p0 + 16 + dx - 1];
            ull q3v = rbp[p0 + 24 + dx - 1];
            ulonglong2 w01 = *(const ulonglong2*)(wb);
            ulonglong2 w23 = *(const ulonglong2*)(wb + 2);
            #pragma unroll
            for (int ci = 0; ci < 16; ci++) {
                ull n0 = q0v, n1 = q1v, n2 = q2v, n3 = q3v;
                ulonglong2 nw01 = w01, nw23 = w23;
                if (ci < 15) {                      // prefetch ci+1
                    const ull* rp = rbp + (ci + 1) * (R1 * PW);
                    n0 = rp[p0 + dx - 1];
                    n1 = rp[p0 + 8 + dx - 1];
                    n2 = rp[p0 + 16 + dx - 1];
                    n3 = rp[p0 + 24 + dx - 1];
                    const ull* wp = wb + (ci + 1) * 16;
                    nw01 = *(const ulonglong2*)(wp);
                    nw23 = *(const ulonglong2*)(wp + 2);
                }
                fma2(acc[0],  w01.x, q0v); fma2(acc[1],  w01.y, q0v);
                fma2(acc[2],  w23.x, q0v); fma2(acc[3],  w23.y, q0v);
                fma2(acc[4],  w01.x, q1v); fma2(acc[5],  w01.y, q1v);
                fma2(acc[6],  w23.x, q1v); fma2(acc[7],  w23.y, q1v);
                fma2(acc[8],  w01.x, q2v); fma2(acc[9],  w01.y, q2v);
                fma2(acc[10], w23.x, q2v); fma2(acc[11], w23.y, q2v);
                fma2(acc[12], w01.x, q3v); fma2(acc[13], w01.y, q3v);
                fma2(acc[14], w23.x, q3v); fma2(acc[15], w23.y, q3v);
                q0v = n0; q1v = n1; q2v = n2; q3v = n3;
                w01 = nw01; w23 = nw23;
            }
        }
    }
    #pragma unroll
    for (int j = 0; j < 4; j++) {
        int co = coB + j;
        ull b2v = su[BFU + 16 + co];
        ull* op = su + S2U + (co * R2 + rr) * PW + 1;
        #pragma unroll
        for (int k = 0; k < 4; k++) {
            ull r = xla_tanh2(acc[4*k + j], b2v);
            op[p0 + 8 * k] = r;
            if (k == 3 && p0 == 7) op[-1] = swap32(r);
            if (k == 0 && p0 == 0) op[32] = swap32(r);
        }
    }
}

// One fused layer. All conv accumulations are single fp32 FMA chains from 0
// in k = (dy, dx, ci) order (ci fastest), bias after — bit-identical to XLA.
__global__ void __launch_bounds__(THREADS, 1)
layer_kernel(float* __restrict__ x,
             const float* __restrict__ w0, const float* __restrict__ b0,
             const float* __restrict__ w1, const float* __restrict__ b1,
             const float* __restrict__ w2, const float* __restrict__ b2,
             int parity)
{
    extern __shared__ ull su[];

    const int tid   = threadIdx.x;
    const int rbase = blockIdx.x * TH;                 // even
    const int xbase = ((int)blockIdx.y) << 12;         // b*4096

    // ---- Phase 0: weights as duplicated (w,w) pairs + packed biases + input ----
    for (int t = tid; t < 2304; t += THREADS) { float w = w1[t]; su[WU1 + t] = pk(w, w); }
    if (tid < 144) {
        float a = w0[tid], b = w2[tid];
        su[WU0 + tid] = pk(a, a);
        su[WU2 + tid] = pk(b, b);
    }
    if (tid >= 160 && tid < 176) { int i = tid - 160; float v = b0[i]; su[BFU + i] = pk(v, v); }
    if (tid >= 192 && tid < 208) { int i = tid - 192; float v = b1[i]; su[BFU + 16 + i] = pk(v, v); }
    if (tid == 224) { float v = b2[0]; su[BFU + 32] = pk(v, v); }

    // packed masked input: entry e of row rr holds pair p = e-1:
    // ( z[gr][p&63], z[gr][(p+32)&63] ), zeroed at non-A sites.
    for (int t = tid; t < RZ * PW; t += THREADS) {
        int rr = t / PW, e = t - rr * PW, p = e - 1;
        int gr = (rbase + rr - 3) & 63;
        int c0 = p & 63, c1 = (p + 32) & 63;
        const float* row = x + xbase + (gr << 6);
        float v0 = row[c0], v1 = row[c1];
        v0 = (((gr + c0) & 1) == parity) ? v0 : 0.0f;
        v1 = (((gr + c1) & 1) == parity) ? v1 : 0.0f;
        su[SZU + t] = pk(v0, v1);
    }
    __syncthreads();

    // ---- Phase 1: conv1 (1 -> 16): EXACTLY 640 tasks (20 rows x 8 pQ x 4 coQ) ----
    conv1_task(su, tid);
    __syncthreads();

    // ---- Phase 2: conv2 (16 -> 16): 576 tasks (18 rows x 8 pQ x 4 coQ) ----
    if (tid < 576) conv2_task(su, tid);
    __syncthreads();

    // ---- Phase 3: conv3 (16 -> 1), chain (dy,dx,ci), bias, STE sign update ----
    // 512 tasks: 16 rows x 32 pairs; pair p0 covers columns (p0, p0+32)
    if (tid < TH * 32) {
        int rr = tid >> 5;
        int p0 = tid & 31;
        ull acc = 0ull;
        #pragma unroll
        for (int dy = 0; dy < 3; dy++) {
            const ull* rbp = su + S2U + (rr + dy) * PW + 1;
            #pragma unroll
            for (int dx = 0; dx < 3; dx++) {
                const ull* wp = su + WU2 + (dy * 3 + dx) * 16;
                // manual 1-deep pipeline
                ull qa = rbp[p0 + dx - 1];
                ull wv = wp[0];
                #pragma unroll
                for (int ci = 0; ci < 16; ci++) {
                    ull nqa = qa, nwv = wv;
                    if (ci < 15) {
                        nqa = rbp[(ci + 1) * (R2 * PW) + p0 + dx - 1];
                        nwv = wp[ci + 1];
                    }
                    fma2(acc, wv, qa);
                    qa = nqa; wv = nwv;
                }
            }
        }
        float bb, dummy;
        upk(su[BFU + 32], bb, dummy);
        float u0, u1;
        upk(acc, u0, u1);
        float l0 = __fadd_rn(u0, bb);
        float l1 = __fadd_rn(u1, bb);
        int gr = rbase + rr;
        // columns p0 and p0+32 share parity -> uniform condition per thread
        if (((gr + p0) & 1) != parity) {
            float* row = x + xbase + (gr << 6);
            float s0 = (l0 > 0.0f) ? 1.0f : ((l0 < 0.0f) ? -1.0f : 0.0f);
            float s1v = (l1 > 0.0f) ? 1.0f : ((l1 < 0.0f) ? -1.0f : 0.0f);
            // STE forward exactly as XLA computes it: l + (sign(l) - l)
            float m0 = __fadd_rn(l0, __fadd_rn(s0, -l0));
            float m1 = __fadd_rn(l1, __fadd_rn(s1v, -l1));
            row[p0]      = __fmul_rn(row[p0],      m0);
            row[p0 + 32] = __fmul_rn(row[p0 + 32], m1);
        }
    }
}

extern "C" void kernel_launch(void* const* d_in, const int* in_sizes, int n_in,
                              void* d_out, int out_size)
{
    const float* z  = (const float*)d_in[0];
    const float* W0 = (const float*)d_in[1];
    const float* b0 = (const float*)d_in[2];
    const float* W1 = (const float*)d_in[3];
    const float* b1 = (const float*)d_in[4];
    const float* W2 = (const float*)d_in[5];
    const float* b2 = (const float*)d_in[6];
    float* x = (float*)d_out;

    cudaFuncSetAttribute(layer_kernel, cudaFuncAttributeMaxDynamicSharedMemorySize,
                         (int)SMEM_BYTES);

    // reset working state each replay: x <- z
    copy_k<<<(Bg * Lg * Lg) / (4 * 256), 256>>>((const float4*)z, (float4*)x);

    for (int i = 0; i < 4; i++) {
        layer_kernel<<<dim3(NTILES, Bg), THREADS, SMEM_BYTES>>>(
            x,
            W0 + i * 144, b0 + i * 16,
            W1 + i * 2304, b1 + i * 16,
            W2 + i * 144, b2 + i,
            i & 1);
    }
}

// round 13
// speedup vs baseline: 1.3966x; 1.1405x over previous
#include <cuda_runtime.h>

typedef unsigned long long ull;

#define Lg 64
#define Bg 1024
#define TH 16
#define NTILES (Lg/TH)          // 4
#define THREADS 640
#define R1 (TH+4)               // 20 conv1 output rows (halo 2)
#define R2 (TH+2)               // 18 conv2 output rows (halo 1)
#define RZ (TH+6)               // 22 input rows (halo 3)
#define PW 34                   // pairs per row: p = -1..32 (wrapped halo)

// ---- shared memory layout (ull units) ----
#define S1U 0                               // 16*20*34 = 10880
#define S2U (S1U + 16*R1*PW)                // 10880 (+9792)
#define SZU (S2U + 16*R2*PW)                // 20672 (+748)
#define WS1 (SZU + RZ*PW)                   // 21420: W1 SCALAR floats (2304 f = 1152 ull)
#define WS0 (WS1 + 1152)                    // 22572: W0 scalar (144 f = 72 ull)
#define WU2 (WS0 + 72)                      // 22644: W2 packed pairs (144 ull)
#define BFU (WU2 + 144)                     // 22788: packed biases (33 ull)
#define U_TOTAL (BFU + 33)                  // 22821
#define SMEM_BYTES ((size_t)U_TOTAL * 8)    // 182568 B

// ---- packed f32x2 helpers (sm_100+) : per-lane exact fp32 ops ----
__device__ __forceinline__ ull pk(float lo, float hi) {
    ull r; asm("mov.b64 %0, {%1, %2};" : "=l"(r) : "f"(lo), "f"(hi)); return r;
}
__device__ __forceinline__ void upk(ull v, float& lo, float& hi) {
    asm("mov.b64 {%0, %1}, %2;" : "=f"(lo), "=f"(hi) : "l"(v));
}
__device__ __forceinline__ void fma2(ull& d, ull a, ull b) {   // d += a*b
    asm("fma.rn.f32x2 %0, %1, %2, %0;" : "+l"(d) : "l"(a), "l"(b));
}
__device__ __forceinline__ void fma2h(ull& d, ull a, ull c) {  // d = d*a + c
    asm("fma.rn.f32x2 %0, %0, %1, %2;" : "+l"(d) : "l"(a), "l"(c));
}
__device__ __forceinline__ ull add2(ull a, ull b) {
    ull r; asm("add.rn.f32x2 %0, %1, %2;" : "=l"(r) : "l"(a), "l"(b)); return r;
}
__device__ __forceinline__ ull mul2(ull a, ull b) {
    ull r; asm("mul.rn.f32x2 %0, %1, %2;" : "=l"(r) : "l"(a), "l"(b)); return r;
}
__device__ __forceinline__ ull dup(float f) { return pk(f, f); }
__device__ __forceinline__ ull swap32(ull v) { return (v >> 32) | (v << 32); }

// Packed XLA EmitFastTanh on an accumulator pair + packed bias.
// Per-lane op sequence identical to the verified scalar replica.
// DO NOT CHANGE the op sequence (bit-exactness vs XLA verified).
__device__ __forceinline__ ull xla_tanh2(ull acc, ull bias2) {
    ull s = add2(acc, bias2);
    float s0, s1; upk(s, s0, s1);
    float xc0 = fminf(fmaxf(s0, -9.0f), 9.0f);
    float xc1 = fminf(fmaxf(s1, -9.0f), 9.0f);
    ull xc = pk(xc0, xc1);
    ull x2 = mul2(xc, xc);
    ull p = dup(-2.76076847742355e-16f);
    fma2h(p, x2, dup( 2.00018790482477e-13f));
    fma2h(p, x2, dup(-8.60467152213735e-11f));
    fma2h(p, x2, dup( 5.12229709037114e-08f));
    fma2h(p, x2, dup( 1.48572235717979e-05f));
    fma2h(p, x2, dup( 6.37261928875436e-04f));
    fma2h(p, x2, dup( 4.89352455891786e-03f));
    ull num = mul2(xc, p);
    ull q = dup(1.19825839466702e-06f);
    fma2h(q, x2, dup(1.18534705686654e-04f));
    fma2h(q, x2, dup(2.26843463243900e-03f));
    fma2h(q, x2, dup(4.89352518554385e-03f));
    float n0, n1, q0, q1;
    upk(num, n0, n1); upk(q, q0, q1);
    float r0 = __fdiv_rn(n0, q0);
    float r1 = __fdiv_rn(n1, q1);
    float t0 = (fabsf(s0) < 0.0004f) ? s0 : r0;
    float t1 = (fabsf(s1) < 0.0004f) ? s1 : r1;
    return pk(t0, t1);
}

__global__ void copy_k(const float4* __restrict__ in, float4* __restrict__ out) {
    int i = blockIdx.x * blockDim.x + threadIdx.x;
    out[i] = in[i];
}

// Task decode (phases 1/2): T -> rr = T>>5 (warp-uniform),
// p0 = (T>>2)&7 (pair base; pairs p0, p0+8, p0+16, p0+24), coQ = T&3.
// 4pp x 4co = 16 acc pairs. Weights loaded as SCALAR float4 (16B for 4 co)
// and duplicated in-register -> 48 B/lane per 16 FMA2 through L1tex.

// conv1 task: chain (dy,dx)
__device__ __forceinline__ void conv1_task(ull* su, int T) {
    int rr = T >> 5;
    int p0 = (T >> 2) & 7;
    int coB = (T & 3) << 2;
    const float* wsf = (const float*)(su + WS0);
    ull acc[16];
    #pragma unroll
    for (int i = 0; i < 16; i++) acc[i] = 0ull;
    #pragma unroll
    for (int dy = 0; dy < 3; dy++) {
        const ull* rp = su + SZU + (rr + dy) * PW + 1;
        #pragma unroll
        for (int dx = 0; dx < 3; dx++) {
            float4 wv = *(const float4*)(wsf + (dy * 3 + dx) * 16 + coB);
            ull w0p = dup(wv.x), w1p = dup(wv.y), w2p = dup(wv.z), w3p = dup(wv.w);
            #pragma unroll
            for (int k = 0; k < 4; k++) {
                ull q = rp[p0 + 8 * k + dx - 1];
                fma2(acc[4*k + 0], w0p, q);
                fma2(acc[4*k + 1], w1p, q);
                fma2(acc[4*k + 2], w2p, q);
                fma2(acc[4*k + 3], w3p, q);
            }
        }
    }
    #pragma unroll
    for (int j = 0; j < 4; j++) {
        int co = coB + j;
        ull b2v = su[BFU + co];
        ull* op = su + S1U + (co * R1 + rr) * PW + 1;
        #pragma unroll
        for (int k = 0; k < 4; k++) {
            ull r = xla_tanh2(acc[4*k + j], b2v);
            op[p0 + 8 * k] = r;
            if (k == 3 && p0 == 7) op[-1] = swap32(r);  // halo = swap(pair 31)
            if (k == 0 && p0 == 0) op[32] = swap32(r);  // halo = swap(pair 0)
        }
    }
}

// conv2 task: chain (dy,dx,ci), ci-loop manually pipelined (depth 1)
__device__ __forceinline__ void conv2_task(ull* su, int T) {
    int rr = T >> 5;
    int p0 = (T >> 2) & 7;
    int coB = (T & 3) << 2;
    const float* wsf = (const float*)(su + WS1);
    ull acc[16];
    #pragma unroll
    for (int i = 0; i < 16; i++) acc[i] = 0ull;
    #pragma unroll
    for (int dy = 0; dy < 3; dy++) {
        const ull* rbp = su + S1U + (rr + dy) * PW + 1;
        #pragma unroll
        for (int dx = 0; dx < 3; dx++) {
            const float* wb = wsf + (dy * 3 + dx) * 256 + coB;
            // pipeline prologue: ci = 0
            ull q0v = rbp[p0 + dx - 1];
            ull q1v = rbp[p0 + 8 + dx - 1];
            ull q2v = rbp[p0 + 16 + dx - 1];
            ull q3v = rbp[p0 + 24 + dx - 1];
            float4 wv = *(const float4*)(wb);
            #pragma unroll
            for (int ci = 0; ci < 16; ci++) {
                ull n0 = q0v, n1 = q1v, n2 = q2v, n3 = q3v;
                float4 nwv = wv;
                if (ci < 15) {                      // prefetch ci+1
                    const ull* rp = rbp + (ci + 1) * (R1 * PW);
                    n0 = rp[p0 + dx - 1];
                    n1 = rp[p0 + 8 + dx - 1];
                    n2 = rp[p0 + 16 + dx - 1];
                    n3 = rp[p0 + 24 + dx - 1];
                    nwv = *(const float4*)(wb + (ci + 1) * 16);
                }
                ull w0p = dup(wv.x), w1p = dup(wv.y), w2p = dup(wv.z), w3p = dup(wv.w);
                fma2(acc[0],  w0p, q0v); fma2(acc[1],  w1p, q0v);
                fma2(acc[2],  w2p, q0v); fma2(acc[3],  w3p, q0v);
                fma2(acc[4],  w0p, q1v); fma2(acc[5],  w1p, q1v);
                fma2(acc[6],  w2p, q1v); fma2(acc[7],  w3p, q1v);
                fma2(acc[8],  w0p, q2v); fma2(acc[9],  w1p, q2v);
                fma2(acc[10], w2p, q2v); fma2(acc[11], w3p, q2v);
                fma2(acc[12], w0p, q3v); fma2(acc[13], w1p, q3v);
                fma2(acc[14], w2p, q3v); fma2(acc[15], w3p, q3v);
                q0v = n0; q1v = n1; q2v = n2; q3v = n3;
                wv = nwv;
            }
        }
    }
    #pragma unroll
    for (int j = 0; j < 4; j++) {
        int co = coB + j;
        ull b2v = su[BFU + 16 + co];
        ull* op = su + S2U + (co * R2 + rr) * PW + 1;
        #pragma unroll
        for (int k = 0; k < 4; k++) {
            ull r = xla_tanh2(acc[4*k + j], b2v);
            op[p0 + 8 * k] = r;
            if (k == 3 && p0 == 7) op[-1] = swap32(r);
            if (k == 0 && p0 == 0) op[32] = swap32(r);
        }
    }
}

// One fused layer. All conv accumulations are single fp32 FMA chains from 0
// in k = (dy, dx, ci) order (ci fastest), bias after — bit-identical to XLA.
__global__ void __launch_bounds__(THREADS, 1)
layer_kernel(float* __restrict__ x,
             const float* __restrict__ w0, const float* __restrict__ b0,
             const float* __restrict__ w1, const float* __restrict__ b1,
             const float* __restrict__ w2, const float* __restrict__ b2,
             int parity)
{
    extern __shared__ ull su[];

    const int tid   = threadIdx.x;
    const int rbase = blockIdx.x * TH;                 // even
    const int xbase = ((int)blockIdx.y) << 12;         // b*4096

    // ---- Phase 0: scalar weights (conv1/conv2), packed W2 + biases, input ----
    {
        float* ws1 = (float*)(su + WS1);
        for (int t = tid; t < 2304; t += THREADS) ws1[t] = w1[t];
    }
    if (tid < 144) {
        ((float*)(su + WS0))[tid] = w0[tid];
        float b = w2[tid];
        su[WU2 + tid] = pk(b, b);
    }
    if (tid >= 160 && tid < 176) { int i = tid - 160; float v = b0[i]; su[BFU + i] = pk(v, v); }
    if (tid >= 192 && tid < 208) { int i = tid - 192; float v = b1[i]; su[BFU + 16 + i] = pk(v, v); }
    if (tid == 224) { float v = b2[0]; su[BFU + 32] = pk(v, v); }

    // packed masked input: entry e of row rr holds pair p = e-1:
    // ( z[gr][p&63], z[gr][(p+32)&63] ), zeroed at non-A sites.
    for (int t = tid; t < RZ * PW; t += THREADS) {
        int rr = t / PW, e = t - rr * PW, p = e - 1;
        int gr = (rbase + rr - 3) & 63;
        int c0 = p & 63, c1 = (p + 32) & 63;
        const float* row = x + xbase + (gr << 6);
        float v0 = row[c0], v1 = row[c1];
        v0 = (((gr + c0) & 1) == parity) ? v0 : 0.0f;
        v1 = (((gr + c1) & 1) == parity) ? v1 : 0.0f;
        su[SZU + t] = pk(v0, v1);
    }
    __syncthreads();

    // ---- Phase 1: conv1 (1 -> 16): EXACTLY 640 tasks (20 rows x 8 pQ x 4 coQ) ----
    conv1_task(su, tid);
    __syncthreads();

    // ---- Phase 2: conv2 (16 -> 16): 576 tasks (18 rows x 8 pQ x 4 coQ) ----
    if (tid < 576) conv2_task(su, tid);
    __syncthreads();

    // ---- Phase 3: conv3 (16 -> 1), chain (dy,dx,ci), bias, STE sign update ----
    // 512 tasks: 16 rows x 32 pairs; pair p0 covers columns (p0, p0+32)
    if (tid < TH * 32) {
        int rr = tid >> 5;
        int p0 = tid & 31;
        ull acc = 0ull;
        #pragma unroll
        for (int dy = 0; dy < 3; dy++) {
            const ull* rbp = su + S2U + (rr + dy) * PW + 1;
            #pragma unroll
            for (int dx = 0; dx < 3; dx++) {
                const ull* wp = su + WU2 + (dy * 3 + dx) * 16;
                // manual 1-deep pipeline
                ull qa = rbp[p0 + dx - 1];
                ull wv = wp[0];
                #pragma unroll
                for (int ci = 0; ci < 16; ci++) {
                    ull nqa = qa, nwv = wv;
                    if (ci < 15) {
                        nqa = rbp[(ci + 1) * (R2 * PW) + p0 + dx - 1];
                        nwv = wp[ci + 1];
                    }
                    fma2(acc, wv, qa);
                    qa = nqa; wv = nwv;
                }
            }
        }
        float bb, dummy;
        upk(su[BFU + 32], bb, dummy);
        float u0, u1;
        upk(acc, u0, u1);
        float l0 = __fadd_rn(u0, bb);
        float l1 = __fadd_rn(u1, bb);
        int gr = rbase + rr;
        // columns p0 and p0+32 share parity -> uniform condition per thread
        if (((gr + p0) & 1) != parity) {
            float* row = x + xbase + (gr << 6);
            float s0 = (l0 > 0.0f) ? 1.0f : ((l0 < 0.0f) ? -1.0f : 0.0f);
            float s1v = (l1 > 0.0f) ? 1.0f : ((l1 < 0.0f) ? -1.0f : 0.0f);
            // STE forward exactly as XLA computes it: l + (sign(l) - l)
            float m0 = __fadd_rn(l0, __fadd_rn(s0, -l0));
            float m1 = __fadd_rn(l1, __fadd_rn(s1v, -l1));
            row[p0]      = __fmul_rn(row[p0],      m0);
            row[p0 + 32] = __fmul_rn(row[p0 + 32], m1);
        }
    }
}

extern "C" void kernel_launch(void* const* d_in, const int* in_sizes, int n_in,
                              void* d_out, int out_size)
{
    const float* z  = (const float*)d_in[0];
    const float* W0 = (const float*)d_in[1];
    const float* b0 = (const float*)d_in[2];
    const float* W1 = (const float*)d_in[3];
    const float* b1 = (const float*)d_in[4];
    const float* W2 = (const float*)d_in[5];
    const float* b2 = (const float*)d_in[6];
    float* x = (float*)d_out;

    cudaFuncSetAttribute(layer_kernel, cudaFuncAttributeMaxDynamicSharedMemorySize,
                         (int)SMEM_BYTES);

    // reset working state each replay: x <- z
    copy_k<<<(Bg * Lg * Lg) / (4 * 256), 256>>>((const float4*)z, (float4*)x);

    for (int i = 0; i < 4; i++) {
        layer_kernel<<<dim3(NTILES, Bg), THREADS, SMEM_BYTES>>>(
            x,
            W0 + i * 144, b0 + i * 16,
            W1 + i * 2304, b1 + i * 16,
            W2 + i * 144, b2 + i,
            i & 1);
    }
}